// round 9
// baseline (speedup 1.0000x reference)
#include <cuda_runtime.h>
#include <cstdint>
#include <cstddef>

#define N_D   128
#define N_H   256
#define N_CAT 256
#define BN_EPS 1e-5f
#define MAXN  100000

// ---------------------------------------------------------------------------
// Scratch
// ---------------------------------------------------------------------------
__device__ __align__(1024) float g_agg[(size_t)MAXN * N_D];   // 51.2 MB
__device__ __align__(1024) float g_h  [(size_t)MAXN * N_H];   // 102.4 MB
__device__ float g_stats[4 * 256];
__device__ __align__(16) uint32_t g_W1t[N_H * N_CAT];  // [n][k]: raw f32 bits, then BN1-folded tf32
__device__ __align__(16) uint32_t g_W2t[N_D * N_H];    // [n][k]: tf32 bits
__device__ float g_b1p[N_H];

// ---------------------------------------------------------------------------
// Helpers
// ---------------------------------------------------------------------------
__device__ __forceinline__ uint32_t f2tf32(float x) {
    uint32_t r;
    asm("cvt.rna.tf32.f32 %0, %1;" : "=r"(r) : "f"(x));
    return r;
}
__device__ __forceinline__ uint32_t smem_u32(const void* p) {
    uint32_t a;
    asm("{ .reg .u64 t; cvta.to.shared.u64 t, %1; cvt.u32.u64 %0, t; }" : "=r"(a) : "l"(p));
    return a;
}
__device__ __forceinline__ void cp16(uint32_t dst, const void* src, bool pred) {
    int sz = pred ? 16 : 0;
    asm volatile("cp.async.cg.shared.global [%0], [%1], 16, %2;"
                 :: "r"(dst), "l"(src), "r"(sz) : "memory");
}
#define CP_COMMIT() asm volatile("cp.async.commit_group;" ::: "memory")
#define CP_WAIT1()  asm volatile("cp.async.wait_group 1;" ::: "memory")
__device__ __forceinline__ void mma_tf32(float d[4], const uint32_t a[4],
                                         const uint32_t b[2]) {
    asm volatile(
        "mma.sync.aligned.m16n8k8.row.col.f32.tf32.tf32.f32 "
        "{%0,%1,%2,%3}, {%4,%5,%6,%7}, {%8,%9}, {%0,%1,%2,%3};"
        : "+f"(d[0]), "+f"(d[1]), "+f"(d[2]), "+f"(d[3])
        : "r"(a[0]), "r"(a[1]), "r"(a[2]), "r"(a[3]), "r"(b[0]), "r"(b[1]));
}

// ---------------------------------------------------------------------------
// Launch 0: zero agg+stats, transpose W1 (raw) and W2 (tf32)
// ---------------------------------------------------------------------------
__global__ void k_zero_prep(size_t n4, const float* __restrict__ W1,
                            const float* __restrict__ W2) {
    size_t i = (size_t)blockIdx.x * blockDim.x + threadIdx.x;
    size_t stride = (size_t)gridDim.x * blockDim.x;
    float4* p = reinterpret_cast<float4*>(g_agg);
    float4 z = make_float4(0.f, 0.f, 0.f, 0.f);
    for (; i < n4; i += stride) p[i] = z;
    int j = blockIdx.x, t = threadIdx.x;
    if (j == 0)
        for (int q = t; q < 4 * 256; q += blockDim.x) g_stats[q] = 0.f;
    if (j < 256)
        g_W1t[(size_t)j * N_CAT + t] = __float_as_uint(W1[(size_t)t * N_H + j]);
    else if (j < 384)
        g_W2t[(size_t)(j - 256) * N_H + t] = f2tf32(W2[(size_t)t * N_D + (j - 256)]);
}

// Launch 1: SpMM, 8 edges/warp, batched gathers (MLP=8)
__global__ void k_spmm(const float* __restrict__ x, const int* __restrict__ rows,
                       const int* __restrict__ cols, const float* __restrict__ vals, int E) {
    int gw = (int)(((size_t)blockIdx.x * blockDim.x + threadIdx.x) >> 5);
    int lane = threadIdx.x & 31;
    int base = gw * 8;
    if (base >= E) return;

    int e = base + (lane & 7);
    bool ev = e < E;
    int c = ev ? cols[e] : 0;
    int r = ev ? rows[e] : 0;
    float v = ev ? vals[e] : 0.f;

    float4 m[8];
    int ri[8];
    float vi[8];
#pragma unroll
    for (int i = 0; i < 8; i++) {
        int ci = __shfl_sync(0xffffffffu, c, i);
        ri[i]  = __shfl_sync(0xffffffffu, r, i);
        vi[i]  = __shfl_sync(0xffffffffu, v, i);
        m[i] = reinterpret_cast<const float4*>(x + (size_t)ci * N_D)[lane];
    }
#pragma unroll
    for (int i = 0; i < 8; i++) {
        if (base + i < E) {
            float* dst = g_agg + (size_t)ri[i] * N_D + lane * 4;
            asm volatile("red.global.add.v4.f32 [%0], {%1,%2,%3,%4};"
                         :: "l"(dst), "f"(vi[i] * m[i].x), "f"(vi[i] * m[i].y),
                            "f"(vi[i] * m[i].z), "f"(vi[i] * m[i].w) : "memory");
        }
    }
}

// Launch 2: column stats of x_cat = [input | g_agg]
__global__ void k_stats_cat(const float* __restrict__ x, int n) {
    int t = threadIdx.x;
    const float* base = (t < N_D) ? (x + t) : (g_agg + (t - N_D));
    float s = 0.f, sq = 0.f;
    for (int r = blockIdx.x; r < n; r += gridDim.x) {
        float v = base[(size_t)r * N_D];
        s += v; sq += v * v;
    }
    atomicAdd(&g_stats[t], s);
    atomicAdd(&g_stats[256 + t], sq);
}

// Launch 3: fold BN1 into W1t (raw->scaled tf32 in place) + b1p
__global__ void k_bnfold(const float* __restrict__ gamma1, const float* __restrict__ beta1,
                         const float* __restrict__ b1, float n_inv) {
    __shared__ float red[256];
    int j = blockIdx.x, t = threadIdx.x;
    float mean = g_stats[t] * n_inv;
    float var  = g_stats[256 + t] * n_inv - mean * mean;
    float sc   = gamma1[t] * rsqrtf(var + BN_EPS);
    float sh   = beta1[t] - mean * sc;
    float w = __uint_as_float(g_W1t[(size_t)j * N_CAT + t]);
    g_W1t[(size_t)j * N_CAT + t] = f2tf32(sc * w);
    red[t] = sh * w;
    __syncthreads();
    for (int s = 128; s > 0; s >>= 1) {
        if (t < s) red[t] += red[t + s];
        __syncthreads();
    }
    if (t == 0) g_b1p[j] = b1[j] + red[0];
}

// ---------------------------------------------------------------------------
// GEMMs: mma.sync m16n8k8 tf32. CTA tile 128x128, 128 threads = 4 warps (2Mx2N),
// warp tile 64x64 (mt=4, nt=8) -> 128 B smem traffic per MMA.
// cp.async 2-stage pipeline, K chunks of 32.
// ---------------------------------------------------------------------------
#define PADW 36
#define A_WORDS (128 * PADW)                   // 4608
#define B_WORDS (128 * PADW)                   // 4608
#define STG_WORDS (A_WORDS + B_WORDS)          // 9216
#define PIPE_BYTES (2 * STG_WORDS * 4)         // 73728
#define G2_SMEM (PIPE_BYTES + 512 * 4)         // 75776

// Launch 4: GEMM1: h = A_folded @ W1t^T + b1p ; fused column stats of h
__global__ __launch_bounds__(128, 2)
void k_gemm1_mma(const float* __restrict__ input, int M) {
    extern __shared__ uint32_t sm[];
    const uint32_t sbase = smem_u32(sm);
    const int tid = threadIdx.x, wid = tid >> 5, lane = tid & 31;
    const int warp_m = wid & 1, warp_n = wid >> 1;
    const int grp = lane >> 2, tig = lane & 3;
    const int block_row = blockIdx.y * 128;
    const int block_col = blockIdx.x * 128;

    float d[4][8][4];
#pragma unroll
    for (int mt = 0; mt < 4; mt++)
#pragma unroll
        for (int nt = 0; nt < 8; nt++)
#pragma unroll
            for (int q = 0; q < 4; q++) d[mt][nt][q] = 0.f;

    auto issue = [&](int c, int s) {
        const float* asrc = (c < 4) ? input : g_agg;
        const int kofs = (c & 3) * 32;
        uint32_t abase = sbase + (s * STG_WORDS) * 4;
        uint32_t bbase = abase + A_WORDS * 4;
#pragma unroll
        for (int i = 0; i < 8; i++) {   // A: 128x32 = 1024 float4
            int f = i * 128 + tid, row = f >> 3, c4 = f & 7;
            bool p = (block_row + row) < M;
            cp16(abase + (row * PADW + c4 * 4) * 4,
                 asrc + (size_t)(block_row + row) * N_D + kofs + c4 * 4, p);
        }
#pragma unroll
        for (int i = 0; i < 8; i++) {   // B: 128x32
            int f = i * 128 + tid, row = f >> 3, c4 = f & 7;
            cp16(bbase + (row * PADW + c4 * 4) * 4,
                 &g_W1t[(size_t)(block_col + row) * N_CAT + c * 32 + c4 * 4], true);
        }
    };

    issue(0, 0); CP_COMMIT();
    issue(1, 1); CP_COMMIT();

    for (int c = 0; c < 8; c++) {
        const int s = c & 1;
        CP_WAIT1();
        __syncthreads();
        const uint32_t* As = sm + s * STG_WORDS;
        const uint32_t* Bs = As + A_WORDS;
#pragma unroll
        for (int ks = 0; ks < 4; ks++) {
            uint32_t a[4][4], b[8][2];
            const int kc = ks * 8 + tig;
#pragma unroll
            for (int mt = 0; mt < 4; mt++) {
                int rb = warp_m * 64 + mt * 16 + grp;
                a[mt][0] = f2tf32(__uint_as_float(As[rb * PADW + kc]));
                a[mt][1] = f2tf32(__uint_as_float(As[(rb + 8) * PADW + kc]));
                a[mt][2] = f2tf32(__uint_as_float(As[rb * PADW + kc + 4]));
                a[mt][3] = f2tf32(__uint_as_float(As[(rb + 8) * PADW + kc + 4]));
            }
#pragma unroll
            for (int nt = 0; nt < 8; nt++) {
                int nb = warp_n * 64 + nt * 8 + grp;
                b[nt][0] = Bs[nb * PADW + kc];
                b[nt][1] = Bs[nb * PADW + kc + 4];
            }
#pragma unroll
            for (int mt = 0; mt < 4; mt++)
#pragma unroll
                for (int nt = 0; nt < 8; nt++) mma_tf32(d[mt][nt], a[mt], b[nt]);
        }
        __syncthreads();
        if (c + 2 < 8) issue(c + 2, s);
        CP_COMMIT();
    }

    // epilogue: +b1p, write g_h, accumulate column sum/sumsq
    float cs[16], cq[16];
#pragma unroll
    for (int i = 0; i < 16; i++) { cs[i] = 0.f; cq[i] = 0.f; }

#pragma unroll
    for (int mt = 0; mt < 4; mt++) {
        int r0 = block_row + warp_m * 64 + mt * 16 + grp;
#pragma unroll
        for (int nt = 0; nt < 8; nt++) {
            int col = block_col + warp_n * 64 + nt * 8 + tig * 2;
            float bx = g_b1p[col], by = g_b1p[col + 1];
            float vx = d[mt][nt][0] + bx, vy = d[mt][nt][1] + by;
            float vz = d[mt][nt][2] + bx, vw = d[mt][nt][3] + by;
            if (r0 < M) {
                *reinterpret_cast<float2*>(&g_h[(size_t)r0 * N_H + col]) = make_float2(vx, vy);
                cs[nt * 2]     += vx;  cq[nt * 2]     += vx * vx;
                cs[nt * 2 + 1] += vy;  cq[nt * 2 + 1] += vy * vy;
            }
            if (r0 + 8 < M) {
                *reinterpret_cast<float2*>(&g_h[(size_t)(r0 + 8) * N_H + col]) = make_float2(vz, vw);
                cs[nt * 2]     += vz;  cq[nt * 2]     += vz * vz;
                cs[nt * 2 + 1] += vw;  cq[nt * 2 + 1] += vw * vw;
            }
        }
    }
#pragma unroll
    for (int i = 0; i < 16; i++) {
        float s = cs[i], q = cq[i];
        s += __shfl_xor_sync(0xffffffffu, s, 4);
        s += __shfl_xor_sync(0xffffffffu, s, 8);
        s += __shfl_xor_sync(0xffffffffu, s, 16);
        q += __shfl_xor_sync(0xffffffffu, q, 4);
        q += __shfl_xor_sync(0xffffffffu, q, 8);
        q += __shfl_xor_sync(0xffffffffu, q, 16);
        if (grp == 0) {
            int col = block_col + warp_n * 64 + (i >> 1) * 8 + tig * 2 + (i & 1);
            atomicAdd(&g_stats[512 + col], s);
            atomicAdd(&g_stats[768 + col], q);
        }
    }
}

// Launch 5: GEMM2: out = relu(h*sc2+sh2) @ W2t^T + b2 ; BN2 params inline
__global__ __launch_bounds__(128, 2)
void k_gemm2_mma(const float* __restrict__ gamma2, const float* __restrict__ beta2,
                 const float* __restrict__ b2, float* __restrict__ out,
                 int M, float n_inv) {
    extern __shared__ uint32_t sm[];
    const uint32_t sbase = smem_u32(sm);
    float* scs = reinterpret_cast<float*>(sm + 2 * STG_WORDS);
    float* shs = scs + 256;
    const int tid = threadIdx.x, wid = tid >> 5, lane = tid & 31;
    const int warp_m = wid & 1, warp_n = wid >> 1;
    const int grp = lane >> 2, tig = lane & 3;
    const int block_row = blockIdx.y * 128;

    for (int k = tid; k < 256; k += 128) {
        float mean = g_stats[512 + k] * n_inv;
        float var  = g_stats[768 + k] * n_inv - mean * mean;
        float sc   = gamma2[k] * rsqrtf(var + BN_EPS);
        scs[k] = sc;
        shs[k] = beta2[k] - mean * sc;
    }

    float d[4][8][4];
#pragma unroll
    for (int mt = 0; mt < 4; mt++)
#pragma unroll
        for (int nt = 0; nt < 8; nt++)
#pragma unroll
            for (int q = 0; q < 4; q++) d[mt][nt][q] = 0.f;

    auto issue = [&](int c, int s) {
        uint32_t abase = sbase + (s * STG_WORDS) * 4;
        uint32_t bbase = abase + A_WORDS * 4;
#pragma unroll
        for (int i = 0; i < 8; i++) {
            int f = i * 128 + tid, row = f >> 3, c4 = f & 7;
            bool p = (block_row + row) < M;
            cp16(abase + (row * PADW + c4 * 4) * 4,
                 &g_h[(size_t)(block_row + row) * N_H + c * 32 + c4 * 4], p);
        }
#pragma unroll
        for (int i = 0; i < 8; i++) {
            int f = i * 128 + tid, row = f >> 3, c4 = f & 7;
            cp16(bbase + (row * PADW + c4 * 4) * 4,
                 &g_W2t[(size_t)row * N_H + c * 32 + c4 * 4], true);
        }
    };

    issue(0, 0); CP_COMMIT();
    issue(1, 1); CP_COMMIT();
    __syncthreads();   // covers scs/shs fill

    for (int c = 0; c < 8; c++) {
        const int s = c & 1;
        CP_WAIT1();
        __syncthreads();
        const uint32_t* As = sm + s * STG_WORDS;
        const uint32_t* Bs = As + A_WORDS;
#pragma unroll
        for (int ks = 0; ks < 4; ks++) {
            uint32_t a[4][4], b[8][2];
            const int kc = ks * 8 + tig;
            const int k0 = c * 32 + kc, k1 = k0 + 4;
            const float sc0 = scs[k0], sh0 = shs[k0];
            const float sc1 = scs[k1], sh1 = shs[k1];
#pragma unroll
            for (int mt = 0; mt < 4; mt++) {
                int rb = warp_m * 64 + mt * 16 + grp;
                float v0 = __uint_as_float(As[rb * PADW + kc]);
                float v1 = __uint_as_float(As[(rb + 8) * PADW + kc]);
                float v2 = __uint_as_float(As[rb * PADW + kc + 4]);
                float v3 = __uint_as_float(As[(rb + 8) * PADW + kc + 4]);
                a[mt][0] = f2tf32(fmaxf(v0 * sc0 + sh0, 0.f));
                a[mt][1] = f2tf32(fmaxf(v1 * sc0 + sh0, 0.f));
                a[mt][2] = f2tf32(fmaxf(v2 * sc1 + sh1, 0.f));
                a[mt][3] = f2tf32(fmaxf(v3 * sc1 + sh1, 0.f));
            }
#pragma unroll
            for (int nt = 0; nt < 8; nt++) {
                int nb = warp_n * 64 + nt * 8 + grp;
                b[nt][0] = Bs[nb * PADW + kc];
                b[nt][1] = Bs[nb * PADW + kc + 4];
            }
#pragma unroll
            for (int mt = 0; mt < 4; mt++)
#pragma unroll
                for (int nt = 0; nt < 8; nt++) mma_tf32(d[mt][nt], a[mt], b[nt]);
        }
        __syncthreads();
        if (c + 2 < 8) issue(c + 2, s);
        CP_COMMIT();
    }

#pragma unroll
    for (int mt = 0; mt < 4; mt++) {
        int r0 = block_row + warp_m * 64 + mt * 16 + grp;
#pragma unroll
        for (int nt = 0; nt < 8; nt++) {
            int col = warp_n * 64 + nt * 8 + tig * 2;
            float bx = b2[col], by = b2[col + 1];
            if (r0 < M)
                *reinterpret_cast<float2*>(&out[(size_t)r0 * N_D + col]) =
                    make_float2(d[mt][nt][0] + bx, d[mt][nt][1] + by);
            if (r0 + 8 < M)
                *reinterpret_cast<float2*>(&out[(size_t)(r0 + 8) * N_D + col]) =
                    make_float2(d[mt][nt][2] + bx, d[mt][nt][3] + by);
        }
    }
}

// ---------------------------------------------------------------------------
// Launch
// ---------------------------------------------------------------------------
extern "C" void kernel_launch(void* const* d_in, const int* in_sizes, int n_in,
                              void* d_out, int out_size) {
    const float* input  = (const float*)d_in[0];
    const int*   rows   = (const int*)  d_in[1];
    const int*   cols   = (const int*)  d_in[2];
    const float* vals   = (const float*)d_in[3];
    const float* gamma1 = (const float*)d_in[4];
    const float* beta1  = (const float*)d_in[5];
    const float* W1     = (const float*)d_in[6];
    const float* b1     = (const float*)d_in[7];
    const float* gamma2 = (const float*)d_in[8];
    const float* beta2  = (const float*)d_in[9];
    const float* W2     = (const float*)d_in[10];
    const float* b2     = (const float*)d_in[11];
    float* out = (float*)d_out;

    const int n = in_sizes[0] / N_D;
    const int E = in_sizes[1];
    const float n_inv = 1.0f / (float)n;

    cudaFuncSetAttribute(k_gemm1_mma, cudaFuncAttributeMaxDynamicSharedMemorySize, PIPE_BYTES);
    cudaFuncSetAttribute(k_gemm2_mma, cudaFuncAttributeMaxDynamicSharedMemorySize, G2_SMEM);

    // 0: zero agg/stats + W transposes
    {
        size_t n4 = (size_t)n * N_D / 4;
        k_zero_prep<<<(int)((n4 + 255) / 256), 256>>>(n4, W1, W2);
    }
    // 1: SpMM
    {
        int warps = (E + 7) / 8;
        k_spmm<<<(warps * 32 + 255) / 256, 256>>>(input, rows, cols, vals, E);
    }
    // 2: stats of x_cat
    k_stats_cat<<<512, 256>>>(input, n);
    // 3: BN1 fold into W1t + b1p
    k_bnfold<<<256, 256>>>(gamma1, beta1, b1, n_inv);
    // 4: GEMM1 (128x128 CTA, 64x64 warp tiles, fused h-stats)
    {
        dim3 grid(2, (n + 127) / 128);
        k_gemm1_mma<<<grid, 128, PIPE_BYTES>>>(input, n);
    }
    // 5: GEMM2 (BN2 inline)
    {
        dim3 grid(1, (n + 127) / 128);
        k_gemm2_mma<<<grid, 128, G2_SMEM>>>(gamma2, beta2, b2, out, n, n_inv);
    }
}

// round 10
// speedup vs baseline: 1.0705x; 1.0705x over previous
#include <cuda_runtime.h>
#include <cstdint>
#include <cstddef>

#define N_D   128
#define N_H   256
#define N_CAT 256
#define BN_EPS 1e-5f
#define MAXN  100000

// ---------------------------------------------------------------------------
// Scratch
// ---------------------------------------------------------------------------
__device__ __align__(1024) float g_agg[(size_t)MAXN * N_D];   // 51.2 MB
__device__ __align__(1024) float g_h  [(size_t)MAXN * N_H];   // 102.4 MB
__device__ float g_stats[4 * 256];
__device__ __align__(16) uint32_t g_W1t[N_H * N_CAT];  // [n][k]: raw f32 bits -> BN1-folded tf32
__device__ __align__(16) uint32_t g_W2t[N_D * N_H];    // [n][k]: tf32 bits
__device__ float g_b1p[N_H];

// ---------------------------------------------------------------------------
// Helpers
// ---------------------------------------------------------------------------
__device__ __forceinline__ uint32_t f2tf32(float x) {
    uint32_t r;
    asm("cvt.rna.tf32.f32 %0, %1;" : "=r"(r) : "f"(x));
    return r;
}
__device__ __forceinline__ uint32_t smem_u32(const void* p) {
    uint32_t a;
    asm("{ .reg .u64 t; cvta.to.shared.u64 t, %1; cvt.u32.u64 %0, t; }" : "=r"(a) : "l"(p));
    return a;
}
__device__ __forceinline__ void cp16(uint32_t dst, const void* src, bool pred) {
    int sz = pred ? 16 : 0;
    asm volatile("cp.async.cg.shared.global [%0], [%1], 16, %2;"
                 :: "r"(dst), "l"(src), "r"(sz) : "memory");
}
#define CP_COMMIT() asm volatile("cp.async.commit_group;" ::: "memory")
#define CP_WAIT2()  asm volatile("cp.async.wait_group 2;" ::: "memory")
__device__ __forceinline__ void mma_tf32(float d[4], const uint32_t a[4],
                                         const uint32_t b[2]) {
    asm volatile(
        "mma.sync.aligned.m16n8k8.row.col.f32.tf32.tf32.f32 "
        "{%0,%1,%2,%3}, {%4,%5,%6,%7}, {%8,%9}, {%0,%1,%2,%3};"
        : "+f"(d[0]), "+f"(d[1]), "+f"(d[2]), "+f"(d[3])
        : "r"(a[0]), "r"(a[1]), "r"(a[2]), "r"(a[3]), "r"(b[0]), "r"(b[1]));
}

// ---------------------------------------------------------------------------
// Launch 0: zero agg+stats, transpose W1 (raw) and W2 (tf32)
// ---------------------------------------------------------------------------
__global__ void k_zero_prep(size_t n4, const float* __restrict__ W1,
                            const float* __restrict__ W2) {
    size_t i = (size_t)blockIdx.x * blockDim.x + threadIdx.x;
    size_t stride = (size_t)gridDim.x * blockDim.x;
    float4* p = reinterpret_cast<float4*>(g_agg);
    float4 z = make_float4(0.f, 0.f, 0.f, 0.f);
    for (; i < n4; i += stride) p[i] = z;
    int j = blockIdx.x, t = threadIdx.x;
    if (j == 0)
        for (int q = t; q < 4 * 256; q += blockDim.x) g_stats[q] = 0.f;
    if (j < 256)
        g_W1t[(size_t)j * N_CAT + t] = __float_as_uint(W1[(size_t)t * N_H + j]);
    else if (j < 384)
        g_W2t[(size_t)(j - 256) * N_H + t] = f2tf32(W2[(size_t)t * N_D + (j - 256)]);
}

// Launch 1: SpMM, 8 edges/warp, batched gathers (MLP=8)
__global__ void k_spmm(const float* __restrict__ x, const int* __restrict__ rows,
                       const int* __restrict__ cols, const float* __restrict__ vals, int E) {
    int gw = (int)(((size_t)blockIdx.x * blockDim.x + threadIdx.x) >> 5);
    int lane = threadIdx.x & 31;
    int base = gw * 8;
    if (base >= E) return;

    int e = base + (lane & 7);
    bool ev = e < E;
    int c = ev ? cols[e] : 0;
    int r = ev ? rows[e] : 0;
    float v = ev ? vals[e] : 0.f;

    float4 m[8];
    int ri[8];
    float vi[8];
#pragma unroll
    for (int i = 0; i < 8; i++) {
        int ci = __shfl_sync(0xffffffffu, c, i);
        ri[i]  = __shfl_sync(0xffffffffu, r, i);
        vi[i]  = __shfl_sync(0xffffffffu, v, i);
        m[i] = reinterpret_cast<const float4*>(x + (size_t)ci * N_D)[lane];
    }
#pragma unroll
    for (int i = 0; i < 8; i++) {
        if (base + i < E) {
            float* dst = g_agg + (size_t)ri[i] * N_D + lane * 4;
            asm volatile("red.global.add.v4.f32 [%0], {%1,%2,%3,%4};"
                         :: "l"(dst), "f"(vi[i] * m[i].x), "f"(vi[i] * m[i].y),
                            "f"(vi[i] * m[i].z), "f"(vi[i] * m[i].w) : "memory");
        }
    }
}

// Launch 2: column stats of x_cat = [input | g_agg]
__global__ void k_stats_cat(const float* __restrict__ x, int n) {
    int t = threadIdx.x;
    const float* base = (t < N_D) ? (x + t) : (g_agg + (t - N_D));
    float s = 0.f, sq = 0.f;
    for (int r = blockIdx.x; r < n; r += gridDim.x) {
        float v = base[(size_t)r * N_D];
        s += v; sq += v * v;
    }
    atomicAdd(&g_stats[t], s);
    atomicAdd(&g_stats[256 + t], sq);
}

// Launch 3: fold BN1 into W1t (raw->scaled tf32 in place) + b1p
__global__ void k_bnfold(const float* __restrict__ gamma1, const float* __restrict__ beta1,
                         const float* __restrict__ b1, float n_inv) {
    __shared__ float red[256];
    int j = blockIdx.x, t = threadIdx.x;
    float mean = g_stats[t] * n_inv;
    float var  = g_stats[256 + t] * n_inv - mean * mean;
    float sc   = gamma1[t] * rsqrtf(var + BN_EPS);
    float sh   = beta1[t] - mean * sc;
    float w = __uint_as_float(g_W1t[(size_t)j * N_CAT + t]);
    g_W1t[(size_t)j * N_CAT + t] = f2tf32(sc * w);
    red[t] = sh * w;
    __syncthreads();
    for (int s = 128; s > 0; s >>= 1) {
        if (t < s) red[t] += red[t + s];
        __syncthreads();
    }
    if (t == 0) g_b1p[j] = b1[j] + red[0];
}

// ---------------------------------------------------------------------------
// Persistent GEMMs, resident-B design.
// CTA: 256 threads = 8 warps (4M x 2N), warp tile 64x64, M-tile 256, N-block 128.
// B panel (128n x 256k f32, swizzled) resident in smem; A streamed 3-stage.
// Smem layout (uint32 words):
//   A stages: 3 x 8192 words (256 rows x 32 words, swizzled)   [0 .. 24576)
//   B panel:  8 chunks x 4096 words (128 rows x 32 words)      [24576 .. 57344)
//   (gemm2) scs/shs: 512 floats                                [57344 .. 57856)
// Swizzle: word(row,k) = row*32 + ((((k>>2) ^ (row&7))<<2) | (k&3))
// ---------------------------------------------------------------------------
#define A_STG_W   8192
#define B_OFF_W   24576
#define B_CHK_W   4096
#define G1_SMEM   ((B_OFF_W + 8 * B_CHK_W) * 4)            // 229376
#define G2_SMEM   ((B_OFF_W + 8 * B_CHK_W + 512) * 4)      // 231424

// Launch 4: GEMM1: h = A_folded @ W1t^T + b1p ; fused column stats of h
__global__ __launch_bounds__(256, 1)
void k_gemm1_mma(const float* __restrict__ input, int M) {
    extern __shared__ uint32_t sm[];
    const uint32_t sbase = smem_u32(sm);
    const int tid = threadIdx.x, wid = tid >> 5, lane = tid & 31;
    const int warp_m = wid & 3, warp_n = wid >> 2;
    const int grp = lane >> 2, tig = lane & 3;
    const int block_col = blockIdx.x * 128;
    const int by = blockIdx.y, bstride = gridDim.y;
    const int ntiles = (M + 255) / 256;
    const int njobs = (ntiles - by + bstride - 1) / bstride;
    const int total_chunks = njobs * 8;

    // --- load resident B panel (once) ---
#pragma unroll
    for (int i = 0; i < 32; i++) {
        int idx = i * 256 + tid;
        int nrow = idx >> 6, kg = idx & 63;
        int chk = kg >> 3, g = kg & 7;
        uint32_t dstw = B_OFF_W + chk * B_CHK_W + nrow * 32 + ((g ^ (nrow & 7)) << 2);
        cp16(sbase + dstw * 4, &g_W1t[(size_t)(block_col + nrow) * N_CAT + kg * 4], true);
    }

    // issue A chunk for linear chunk index L into stage L%3
    auto issueA = [&](int L) {
        int c = L & 7;
        int trow = (by + (L >> 3) * bstride) * 256;
        const float* asrc = (c < 4) ? input : g_agg;
        int kofs = (c & 3) * 32;
        uint32_t abase = sbase + ((L % 3) * A_STG_W) * 4;
#pragma unroll
        for (int i = 0; i < 8; i++) {
            int idx = i * 256 + tid, row = idx >> 3, g = idx & 7;
            bool p = (trow + row) < M;
            uint32_t dstw = row * 32 + ((g ^ (row & 7)) << 2);
            cp16(abase + dstw * 4,
                 asrc + (size_t)(trow + row) * N_D + kofs + g * 4, p);
        }
    };

    issueA(0); CP_COMMIT();          // group: B + A0
    if (total_chunks > 1) issueA(1);
    CP_COMMIT();
    if (total_chunks > 2) issueA(2);
    CP_COMMIT();

    float d[4][8][4];
#pragma unroll
    for (int mt = 0; mt < 4; mt++)
#pragma unroll
        for (int nt = 0; nt < 8; nt++)
#pragma unroll
            for (int q = 0; q < 4; q++) d[mt][nt][q] = 0.f;

    float cs[16], cq[16];
#pragma unroll
    for (int i = 0; i < 16; i++) { cs[i] = 0.f; cq[i] = 0.f; }

    const int rb0 = warp_m * 64 + grp;
    const int nb0 = warp_n * 64 + grp;

    for (int L = 0; L < total_chunks; L++) {
        CP_WAIT2();
        __syncthreads();
        const uint32_t* As = sm + (L % 3) * A_STG_W;
        const uint32_t* Bs = sm + B_OFF_W + (L & 7) * B_CHK_W;
#pragma unroll
        for (int ks = 0; ks < 4; ks++) {
            const int wo0 = (((2 * ks) ^ grp) << 2) | tig;
            const int wo1 = (((2 * ks + 1) ^ grp) << 2) | tig;
            uint32_t a[4][4], b[8][2];
#pragma unroll
            for (int mt = 0; mt < 4; mt++) {
                int rb = (rb0 + mt * 16) * 32;
                a[mt][0] = f2tf32(__uint_as_float(As[rb + wo0]));
                a[mt][1] = f2tf32(__uint_as_float(As[rb + 256 + wo0]));
                a[mt][2] = f2tf32(__uint_as_float(As[rb + wo1]));
                a[mt][3] = f2tf32(__uint_as_float(As[rb + 256 + wo1]));
            }
#pragma unroll
            for (int nt = 0; nt < 8; nt++) {
                int nb = (nb0 + nt * 8) * 32;
                b[nt][0] = Bs[nb + wo0];
                b[nt][1] = Bs[nb + wo1];
            }
#pragma unroll
            for (int mt = 0; mt < 4; mt++)
#pragma unroll
                for (int nt = 0; nt < 8; nt++) mma_tf32(d[mt][nt], a[mt], b[nt]);
        }
        __syncthreads();
        if (L + 3 < total_chunks) issueA(L + 3);
        CP_COMMIT();

        if ((L & 7) == 7) {
            // epilogue for this tile: +b1p, write g_h, accumulate stats
            int trow = (by + (L >> 3) * bstride) * 256;
#pragma unroll
            for (int mt = 0; mt < 4; mt++) {
                int r0 = trow + warp_m * 64 + mt * 16 + grp;
#pragma unroll
                for (int nt = 0; nt < 8; nt++) {
                    int col = block_col + warp_n * 64 + nt * 8 + tig * 2;
                    float bx = g_b1p[col], by2 = g_b1p[col + 1];
                    float vx = d[mt][nt][0] + bx, vy = d[mt][nt][1] + by2;
                    float vz = d[mt][nt][2] + bx, vw = d[mt][nt][3] + by2;
                    if (r0 < M) {
                        *reinterpret_cast<float2*>(&g_h[(size_t)r0 * N_H + col]) =
                            make_float2(vx, vy);
                        cs[nt * 2]     += vx;  cq[nt * 2]     += vx * vx;
                        cs[nt * 2 + 1] += vy;  cq[nt * 2 + 1] += vy * vy;
                    }
                    if (r0 + 8 < M) {
                        *reinterpret_cast<float2*>(&g_h[(size_t)(r0 + 8) * N_H + col]) =
                            make_float2(vz, vw);
                        cs[nt * 2]     += vz;  cq[nt * 2]     += vz * vz;
                        cs[nt * 2 + 1] += vw;  cq[nt * 2 + 1] += vw * vw;
                    }
                    d[mt][nt][0] = 0.f; d[mt][nt][1] = 0.f;
                    d[mt][nt][2] = 0.f; d[mt][nt][3] = 0.f;
                }
            }
        }
    }

    // one atomic set per CTA
#pragma unroll
    for (int i = 0; i < 16; i++) {
        float s = cs[i], q = cq[i];
        s += __shfl_xor_sync(0xffffffffu, s, 4);
        s += __shfl_xor_sync(0xffffffffu, s, 8);
        s += __shfl_xor_sync(0xffffffffu, s, 16);
        q += __shfl_xor_sync(0xffffffffu, q, 4);
        q += __shfl_xor_sync(0xffffffffu, q, 8);
        q += __shfl_xor_sync(0xffffffffu, q, 16);
        if (grp == 0) {
            int col = block_col + warp_n * 64 + (i >> 1) * 8 + tig * 2 + (i & 1);
            atomicAdd(&g_stats[512 + col], s);
            atomicAdd(&g_stats[768 + col], q);
        }
    }
}

// Launch 5: GEMM2: out = relu(h*sc2+sh2) @ W2t^T + b2 ; BN2 params inline
__global__ __launch_bounds__(256, 1)
void k_gemm2_mma(const float* __restrict__ gamma2, const float* __restrict__ beta2,
                 const float* __restrict__ b2, float* __restrict__ out,
                 int M, float n_inv) {
    extern __shared__ uint32_t sm[];
    const uint32_t sbase = smem_u32(sm);
    float* scs = reinterpret_cast<float*>(sm + B_OFF_W + 8 * B_CHK_W);
    float* shs = scs + 256;
    const int tid = threadIdx.x, wid = tid >> 5, lane = tid & 31;
    const int warp_m = wid & 3, warp_n = wid >> 2;
    const int grp = lane >> 2, tig = lane & 3;
    const int by = blockIdx.y, bstride = gridDim.y;
    const int ntiles = (M + 255) / 256;
    const int njobs = (ntiles - by + bstride - 1) / bstride;
    const int total_chunks = njobs * 8;

    if (tid < 256) {
        float mean = g_stats[512 + tid] * n_inv;
        float var  = g_stats[768 + tid] * n_inv - mean * mean;
        float sc   = gamma2[tid] * rsqrtf(var + BN_EPS);
        scs[tid] = sc;
        shs[tid] = beta2[tid] - mean * sc;
    }

    // resident B panel: W2t (128 n x 256 k)
#pragma unroll
    for (int i = 0; i < 32; i++) {
        int idx = i * 256 + tid;
        int nrow = idx >> 6, kg = idx & 63;
        int chk = kg >> 3, g = kg & 7;
        uint32_t dstw = B_OFF_W + chk * B_CHK_W + nrow * 32 + ((g ^ (nrow & 7)) << 2);
        cp16(sbase + dstw * 4, &g_W2t[(size_t)nrow * N_H + kg * 4], true);
    }

    auto issueA = [&](int L) {
        int c = L & 7;
        int trow = (by + (L >> 3) * bstride) * 256;
        uint32_t abase = sbase + ((L % 3) * A_STG_W) * 4;
#pragma unroll
        for (int i = 0; i < 8; i++) {
            int idx = i * 256 + tid, row = idx >> 3, g = idx & 7;
            bool p = (trow + row) < M;
            uint32_t dstw = row * 32 + ((g ^ (row & 7)) << 2);
            cp16(abase + dstw * 4,
                 &g_h[(size_t)(trow + row) * N_H + c * 32 + g * 4], p);
        }
    };

    issueA(0); CP_COMMIT();
    if (total_chunks > 1) issueA(1);
    CP_COMMIT();
    if (total_chunks > 2) issueA(2);
    CP_COMMIT();

    float d[4][8][4];
#pragma unroll
    for (int mt = 0; mt < 4; mt++)
#pragma unroll
        for (int nt = 0; nt < 8; nt++)
#pragma unroll
            for (int q = 0; q < 4; q++) d[mt][nt][q] = 0.f;

    const int rb0 = warp_m * 64 + grp;
    const int nb0 = warp_n * 64 + grp;

    for (int L = 0; L < total_chunks; L++) {
        CP_WAIT2();
        __syncthreads();
        const uint32_t* As = sm + (L % 3) * A_STG_W;
        const uint32_t* Bs = sm + B_OFF_W + (L & 7) * B_CHK_W;
        const int c = L & 7;
#pragma unroll
        for (int ks = 0; ks < 4; ks++) {
            const int wo0 = (((2 * ks) ^ grp) << 2) | tig;
            const int wo1 = (((2 * ks + 1) ^ grp) << 2) | tig;
            const int k0 = c * 32 + ks * 8 + tig, k1 = k0 + 4;
            const float sc0 = scs[k0], sh0 = shs[k0];
            const float sc1 = scs[k1], sh1 = shs[k1];
            uint32_t a[4][4], b[8][2];
#pragma unroll
            for (int mt = 0; mt < 4; mt++) {
                int rb = (rb0 + mt * 16) * 32;
                float v0 = __uint_as_float(As[rb + wo0]);
                float v1 = __uint_as_float(As[rb + 256 + wo0]);
                float v2 = __uint_as_float(As[rb + wo1]);
                float v3 = __uint_as_float(As[rb + 256 + wo1]);
                a[mt][0] = f2tf32(fmaxf(v0 * sc0 + sh0, 0.f));
                a[mt][1] = f2tf32(fmaxf(v1 * sc0 + sh0, 0.f));
                a[mt][2] = f2tf32(fmaxf(v2 * sc1 + sh1, 0.f));
                a[mt][3] = f2tf32(fmaxf(v3 * sc1 + sh1, 0.f));
            }
#pragma unroll
            for (int nt = 0; nt < 8; nt++) {
                int nb = (nb0 + nt * 8) * 32;
                b[nt][0] = Bs[nb + wo0];
                b[nt][1] = Bs[nb + wo1];
            }
#pragma unroll
            for (int mt = 0; mt < 4; mt++)
#pragma unroll
                for (int nt = 0; nt < 8; nt++) mma_tf32(d[mt][nt], a[mt], b[nt]);
        }
        __syncthreads();
        if (L + 3 < total_chunks) issueA(L + 3);
        CP_COMMIT();

        if ((L & 7) == 7) {
            int trow = (by + (L >> 3) * bstride) * 256;
#pragma unroll
            for (int mt = 0; mt < 4; mt++) {
                int r0 = trow + warp_m * 64 + mt * 16 + grp;
#pragma unroll
                for (int nt = 0; nt < 8; nt++) {
                    int col = warp_n * 64 + nt * 8 + tig * 2;
                    float bx = b2[col], by2 = b2[col + 1];
                    if (r0 < M)
                        *reinterpret_cast<float2*>(&out[(size_t)r0 * N_D + col]) =
                            make_float2(d[mt][nt][0] + bx, d[mt][nt][1] + by2);
                    if (r0 + 8 < M)
                        *reinterpret_cast<float2*>(&out[(size_t)(r0 + 8) * N_D + col]) =
                            make_float2(d[mt][nt][2] + bx, d[mt][nt][3] + by2);
                    d[mt][nt][0] = 0.f; d[mt][nt][1] = 0.f;
                    d[mt][nt][2] = 0.f; d[mt][nt][3] = 0.f;
                }
            }
        }
    }
}

// ---------------------------------------------------------------------------
// Launch
// ---------------------------------------------------------------------------
extern "C" void kernel_launch(void* const* d_in, const int* in_sizes, int n_in,
                              void* d_out, int out_size) {
    const float* input  = (const float*)d_in[0];
    const int*   rows   = (const int*)  d_in[1];
    const int*   cols   = (const int*)  d_in[2];
    const float* vals   = (const float*)d_in[3];
    const float* gamma1 = (const float*)d_in[4];
    const float* beta1  = (const float*)d_in[5];
    const float* W1     = (const float*)d_in[6];
    const float* b1     = (const float*)d_in[7];
    const float* gamma2 = (const float*)d_in[8];
    const float* beta2  = (const float*)d_in[9];
    const float* W2     = (const float*)d_in[10];
    const float* b2     = (const float*)d_in[11];
    float* out = (float*)d_out;

    const int n = in_sizes[0] / N_D;
    const int E = in_sizes[1];
    const float n_inv = 1.0f / (float)n;

    cudaFuncSetAttribute(k_gemm1_mma, cudaFuncAttributeMaxDynamicSharedMemorySize, G1_SMEM);
    cudaFuncSetAttribute(k_gemm2_mma, cudaFuncAttributeMaxDynamicSharedMemorySize, G2_SMEM);

    // 0: zero agg/stats + W transposes
    {
        size_t n4 = (size_t)n * N_D / 4;
        k_zero_prep<<<(int)((n4 + 255) / 256), 256>>>(n4, W1, W2);
    }
    // 1: SpMM
    {
        int warps = (E + 7) / 8;
        k_spmm<<<(warps * 32 + 255) / 256, 256>>>(input, rows, cols, vals, E);
    }
    // 2: stats of x_cat
    k_stats_cat<<<512, 256>>>(input, n);
    // 3: BN1 fold into W1t + b1p
    k_bnfold<<<256, 256>>>(gamma1, beta1, b1, n_inv);
    // 4: GEMM1 persistent, resident-B (2 N-blocks x 74 CTAs)
    {
        dim3 grid(2, 74);
        k_gemm1_mma<<<grid, 256, G1_SMEM>>>(input, n);
    }
    // 5: GEMM2 persistent, resident-B (1 x 148 CTAs)
    {
        dim3 grid(1, 148);
        k_gemm2_mma<<<grid, 256, G2_SMEM>>>(gamma2, beta2, b2, out, n, n_inv);
    }
}

// round 11
// speedup vs baseline: 1.1943x; 1.1157x over previous
#include <cuda_runtime.h>
#include <cuda_fp16.h>
#include <cstdint>
#include <cstddef>

#define N_D   128
#define N_H   256
#define N_CAT 256
#define BN_EPS 1e-5f
#define MAXN  100000

// ---------------------------------------------------------------------------
// Scratch
// ---------------------------------------------------------------------------
__device__ __align__(1024) float    g_agg[(size_t)MAXN * N_D];   // 51.2 MB f32
__device__ __align__(1024) uint32_t g_xh [(size_t)MAXN * 128];   // 51.2 MB fp16 x_cat (128 half2/row)
__device__ __align__(1024) uint32_t g_h16[(size_t)MAXN * 128];   // 51.2 MB fp16 h
__device__ float g_stats[4 * 256];
__device__ __align__(16) uint32_t g_W1t[N_H * N_CAT];   // staged raw W1^T (f32 bits)
__device__ __align__(16) uint32_t g_W1h[N_H * 128];     // BN1-folded W1^T fp16 pairs
__device__ __align__(16) uint32_t g_W2h[N_D * 128];     // W2^T fp16 pairs
__device__ float g_b1p[N_H];

// ---------------------------------------------------------------------------
// Helpers
// ---------------------------------------------------------------------------
__device__ __forceinline__ uint32_t smem_u32(const void* p) {
    uint32_t a;
    asm("{ .reg .u64 t; cvta.to.shared.u64 t, %1; cvt.u32.u64 %0, t; }" : "=r"(a) : "l"(p));
    return a;
}
__device__ __forceinline__ void cp16(uint32_t dst, const void* src, bool pred) {
    int sz = pred ? 16 : 0;
    asm volatile("cp.async.cg.shared.global [%0], [%1], 16, %2;"
                 :: "r"(dst), "l"(src), "r"(sz) : "memory");
}
#define CP_COMMIT() asm volatile("cp.async.commit_group;" ::: "memory")
#define CP_WAIT2()  asm volatile("cp.async.wait_group 2;" ::: "memory")
__device__ __forceinline__ uint32_t packh2(float x, float y) {
    __half2 h = __floats2half2_rn(x, y);
    return *reinterpret_cast<uint32_t*>(&h);
}
__device__ __forceinline__ void mma_f16(float d[4], const uint32_t a[4],
                                        const uint32_t b[2]) {
    asm volatile(
        "mma.sync.aligned.m16n8k16.row.col.f32.f16.f16.f32 "
        "{%0,%1,%2,%3}, {%4,%5,%6,%7}, {%8,%9}, {%0,%1,%2,%3};"
        : "+f"(d[0]), "+f"(d[1]), "+f"(d[2]), "+f"(d[3])
        : "r"(a[0]), "r"(a[1]), "r"(a[2]), "r"(a[3]), "r"(b[0]), "r"(b[1]));
}

// ---------------------------------------------------------------------------
// Launch 0: zero agg+stats, stage raw W1^T, pack W2^T fp16
// ---------------------------------------------------------------------------
__global__ void k_zero_prep(size_t n4, const float* __restrict__ W1,
                            const float* __restrict__ W2) {
    size_t i = (size_t)blockIdx.x * blockDim.x + threadIdx.x;
    size_t stride = (size_t)gridDim.x * blockDim.x;
    float4* p = reinterpret_cast<float4*>(g_agg);
    float4 z = make_float4(0.f, 0.f, 0.f, 0.f);
    for (; i < n4; i += stride) p[i] = z;
    int j = blockIdx.x, t = threadIdx.x;
    if (j == 0)
        for (int q = t; q < 4 * 256; q += blockDim.x) g_stats[q] = 0.f;
    if (j < 256) {
        g_W1t[(size_t)j * N_CAT + t] = __float_as_uint(W1[(size_t)t * N_H + j]);
    } else if (j < 384 && t < 128) {
        int n = j - 256;
        float w0 = W2[(size_t)(2 * t) * N_D + n];
        float w1 = W2[(size_t)(2 * t + 1) * N_D + n];
        g_W2h[(size_t)n * 128 + t] = packh2(w0, w1);
    }
}

// Launch 1: SpMM, 8 edges/warp, batched gathers (MLP=8)
__global__ void k_spmm(const float* __restrict__ x, const int* __restrict__ rows,
                       const int* __restrict__ cols, const float* __restrict__ vals, int E) {
    int gw = (int)(((size_t)blockIdx.x * blockDim.x + threadIdx.x) >> 5);
    int lane = threadIdx.x & 31;
    int base = gw * 8;
    if (base >= E) return;

    int e = base + (lane & 7);
    bool ev = e < E;
    int c = ev ? cols[e] : 0;
    int r = ev ? rows[e] : 0;
    float v = ev ? vals[e] : 0.f;

    float4 m[8];
    int ri[8];
    float vi[8];
#pragma unroll
    for (int i = 0; i < 8; i++) {
        int ci = __shfl_sync(0xffffffffu, c, i);
        ri[i]  = __shfl_sync(0xffffffffu, r, i);
        vi[i]  = __shfl_sync(0xffffffffu, v, i);
        m[i] = reinterpret_cast<const float4*>(x + (size_t)ci * N_D)[lane];
    }
#pragma unroll
    for (int i = 0; i < 8; i++) {
        if (base + i < E) {
            float* dst = g_agg + (size_t)ri[i] * N_D + lane * 4;
            asm volatile("red.global.add.v4.f32 [%0], {%1,%2,%3,%4};"
                         :: "l"(dst), "f"(vi[i] * m[i].x), "f"(vi[i] * m[i].y),
                            "f"(vi[i] * m[i].z), "f"(vi[i] * m[i].w) : "memory");
        }
    }
}

// Launch 2: column stats of x_cat + write fp16 copy g_xh. 128 thr, 2 cols each.
__global__ void k_stats_cat(const float* __restrict__ x, int n) {
    int t = threadIdx.x;   // 0..127 -> cols 2t, 2t+1
    float s0 = 0.f, q0 = 0.f, s1 = 0.f, q1 = 0.f;
    bool first = t < 64;
    for (int r = blockIdx.x; r < n; r += gridDim.x) {
        float2 v;
        if (first)
            v = *reinterpret_cast<const float2*>(x + (size_t)r * N_D + 2 * t);
        else
            v = *reinterpret_cast<const float2*>(g_agg + (size_t)r * N_D + (2 * t - 128));
        s0 += v.x; q0 += v.x * v.x;
        s1 += v.y; q1 += v.y * v.y;
        g_xh[(size_t)r * 128 + t] = packh2(v.x, v.y);
    }
    atomicAdd(&g_stats[2 * t], s0);
    atomicAdd(&g_stats[2 * t + 1], s1);
    atomicAdd(&g_stats[256 + 2 * t], q0);
    atomicAdd(&g_stats[256 + 2 * t + 1], q1);
}

// Launch 3: fold BN1 into W1 -> g_W1h fp16 pairs + b1p
__global__ void k_bnfold(const float* __restrict__ gamma1, const float* __restrict__ beta1,
                         const float* __restrict__ b1, float n_inv) {
    __shared__ float sw[256];
    __shared__ float red[256];
    int j = blockIdx.x, t = threadIdx.x;
    float mean = g_stats[t] * n_inv;
    float var  = g_stats[256 + t] * n_inv - mean * mean;
    float sc   = gamma1[t] * rsqrtf(var + BN_EPS);
    float sh   = beta1[t] - mean * sc;
    float w = __uint_as_float(g_W1t[(size_t)j * N_CAT + t]);
    sw[t] = sc * w;
    red[t] = sh * w;
    __syncthreads();
    if (t < 128) g_W1h[(size_t)j * 128 + t] = packh2(sw[2 * t], sw[2 * t + 1]);
    for (int s = 128; s > 0; s >>= 1) {
        if (t < s) red[t] += red[t + s];
        __syncthreads();
    }
    if (t == 0) g_b1p[j] = b1[j] + red[0];
}

// ---------------------------------------------------------------------------
// Persistent fp16 GEMMs, resident-B.
// CTA 256 thr = 8 warps (4M x 2N), warp tile 64x64, M-tile 256, N-block 128.
// A: fp16 half2 smem, 3 stages of 256 rows x 16 words. B: 8 chunks x 128 x 16.
// Swizzle: w' = w ^ ((row & 6) << 1), w in [0,16) per chunk.
// mma m16n8k16: slab s of chunk -> words w0 = s*8+tig, w1 = w0+4.
// ---------------------------------------------------------------------------
#define A_STG_W   4096
#define B_OFF_W   12288
#define B_CHK_W   2048
#define G1_SMEM   ((B_OFF_W + 8 * B_CHK_W) * 4)            // 114688
#define G2_SMEM   ((B_OFF_W + 8 * B_CHK_W + 256) * 4)      // +scs2/shs2

// Launch 4: GEMM1: h = xh @ W1h^T + b1p ; writes g_h16 fp16; fused h-stats
__global__ __launch_bounds__(256, 1)
void k_gemm1_mma(int M) {
    extern __shared__ uint32_t sm[];
    const uint32_t sbase = smem_u32(sm);
    const int tid = threadIdx.x, wid = tid >> 5, lane = tid & 31;
    const int warp_m = wid & 3, warp_n = wid >> 2;
    const int grp = lane >> 2, tig = lane & 3;
    const int block_col = blockIdx.x * 128;
    const int by = blockIdx.y, bstride = gridDim.y;
    const int ntiles = (M + 255) / 256;
    const int total_chunks = ((ntiles - by + bstride - 1) / bstride) * 8;

    // resident B panel: g_W1h rows [block_col, block_col+128)
#pragma unroll
    for (int i = 0; i < 16; i++) {
        int idx = i * 256 + tid;           // 4096 cp16
        int nrow = idx >> 5, blk = idx & 31;
        int chk = blk >> 2, j = blk & 3;
        uint32_t dw = B_OFF_W + chk * B_CHK_W + nrow * 16 + ((4 * j) ^ ((nrow & 6) << 1));
        cp16(sbase + dw * 4, &g_W1h[(size_t)(block_col + nrow) * 128 + blk * 4], true);
    }

    auto issueA = [&](int L) {
        int c = L & 7;
        int trow = (by + (L >> 3) * bstride) * 256;
        uint32_t abase = sbase + ((L % 3) * A_STG_W) * 4;
#pragma unroll
        for (int i = 0; i < 4; i++) {
            int idx = i * 256 + tid, row = idx >> 2, j = idx & 3;
            bool p = (trow + row) < M;
            uint32_t dw = row * 16 + ((4 * j) ^ ((row & 6) << 1));
            cp16(abase + dw * 4, &g_xh[(size_t)(trow + row) * 128 + c * 16 + 4 * j], p);
        }
    };

    issueA(0); CP_COMMIT();
    issueA(1); CP_COMMIT();
    issueA(2); CP_COMMIT();

    float d[4][8][4];
#pragma unroll
    for (int mt = 0; mt < 4; mt++)
#pragma unroll
        for (int nt = 0; nt < 8; nt++)
#pragma unroll
            for (int q = 0; q < 4; q++) d[mt][nt][q] = 0.f;

    float cs[16], cq[16];
#pragma unroll
    for (int i = 0; i < 16; i++) { cs[i] = 0.f; cq[i] = 0.f; }

    const int rb0 = warp_m * 64 + grp;
    const int nb0 = warp_n * 64 + grp;

    for (int L = 0; L < total_chunks; L++) {
        CP_WAIT2();
        __syncthreads();
        const uint32_t* As = sm + (L % 3) * A_STG_W;
        const uint32_t* Bs = sm + B_OFF_W + (L & 7) * B_CHK_W;
#pragma unroll
        for (int s = 0; s < 2; s++) {
            const int w0 = s * 8 + tig, w1 = w0 + 4;
            uint32_t a[4][4], b[8][2];
#pragma unroll
            for (int mt = 0; mt < 4; mt++) {
                int r = rb0 + mt * 16;
                int s0 = (r & 6) << 1, s1 = ((r + 8) & 6) << 1;
                a[mt][0] = As[r * 16 + (w0 ^ s0)];
                a[mt][1] = As[(r + 8) * 16 + (w0 ^ s1)];
                a[mt][2] = As[r * 16 + (w1 ^ s0)];
                a[mt][3] = As[(r + 8) * 16 + (w1 ^ s1)];
            }
#pragma unroll
            for (int nt = 0; nt < 8; nt++) {
                int nb = nb0 + nt * 8;
                int sn = (nb & 6) << 1;
                b[nt][0] = Bs[nb * 16 + (w0 ^ sn)];
                b[nt][1] = Bs[nb * 16 + (w1 ^ sn)];
            }
#pragma unroll
            for (int mt = 0; mt < 4; mt++)
#pragma unroll
                for (int nt = 0; nt < 8; nt++) mma_f16(d[mt][nt], a[mt], b[nt]);
        }
        __syncthreads();
        if (L + 3 < total_chunks) issueA(L + 3);
        CP_COMMIT();

        if ((L & 7) == 7) {
            int trow = (by + (L >> 3) * bstride) * 256;
#pragma unroll
            for (int mt = 0; mt < 4; mt++) {
                int r0 = trow + warp_m * 64 + mt * 16 + grp;
#pragma unroll
                for (int nt = 0; nt < 8; nt++) {
                    int col = block_col + warp_n * 64 + nt * 8 + tig * 2;
                    float bx = g_b1p[col], by2 = g_b1p[col + 1];
                    float vx = d[mt][nt][0] + bx, vy = d[mt][nt][1] + by2;
                    float vz = d[mt][nt][2] + bx, vw = d[mt][nt][3] + by2;
                    if (r0 < M) {
                        g_h16[(size_t)r0 * 128 + (col >> 1)] = packh2(vx, vy);
                        cs[nt * 2]     += vx;  cq[nt * 2]     += vx * vx;
                        cs[nt * 2 + 1] += vy;  cq[nt * 2 + 1] += vy * vy;
                    }
                    if (r0 + 8 < M) {
                        g_h16[(size_t)(r0 + 8) * 128 + (col >> 1)] = packh2(vz, vw);
                        cs[nt * 2]     += vz;  cq[nt * 2]     += vz * vz;
                        cs[nt * 2 + 1] += vw;  cq[nt * 2 + 1] += vw * vw;
                    }
                    d[mt][nt][0] = 0.f; d[mt][nt][1] = 0.f;
                    d[mt][nt][2] = 0.f; d[mt][nt][3] = 0.f;
                }
            }
        }
    }

#pragma unroll
    for (int i = 0; i < 16; i++) {
        float s = cs[i], q = cq[i];
        s += __shfl_xor_sync(0xffffffffu, s, 4);
        s += __shfl_xor_sync(0xffffffffu, s, 8);
        s += __shfl_xor_sync(0xffffffffu, s, 16);
        q += __shfl_xor_sync(0xffffffffu, q, 4);
        q += __shfl_xor_sync(0xffffffffu, q, 8);
        q += __shfl_xor_sync(0xffffffffu, q, 16);
        if (grp == 0) {
            int col = block_col + warp_n * 64 + (i >> 1) * 8 + tig * 2 + (i & 1);
            atomicAdd(&g_stats[512 + col], s);
            atomicAdd(&g_stats[768 + col], q);
        }
    }
}

// Launch 5: GEMM2: out = relu(h*sc2+sh2) @ W2h^T + b2 ; BN2 in fp16 (HFMA2)
__global__ __launch_bounds__(256, 1)
void k_gemm2_mma(const float* __restrict__ gamma2, const float* __restrict__ beta2,
                 const float* __restrict__ b2, float* __restrict__ out,
                 int M, float n_inv) {
    extern __shared__ uint32_t sm[];
    const uint32_t sbase = smem_u32(sm);
    __half2* scs2 = reinterpret_cast<__half2*>(sm + B_OFF_W + 8 * B_CHK_W);
    __half2* shs2 = scs2 + 128;
    const int tid = threadIdx.x, wid = tid >> 5, lane = tid & 31;
    const int warp_m = wid & 3, warp_n = wid >> 2;
    const int grp = lane >> 2, tig = lane & 3;
    const int by = blockIdx.y, bstride = gridDim.y;
    const int ntiles = (M + 255) / 256;
    const int total_chunks = ((ntiles - by + bstride - 1) / bstride) * 8;

    if (tid < 128) {
        int k0 = 2 * tid, k1 = k0 + 1;
        float m0 = g_stats[512 + k0] * n_inv;
        float v0 = g_stats[768 + k0] * n_inv - m0 * m0;
        float s0 = gamma2[k0] * rsqrtf(v0 + BN_EPS);
        float t0 = beta2[k0] - m0 * s0;
        float m1 = g_stats[512 + k1] * n_inv;
        float v1 = g_stats[768 + k1] * n_inv - m1 * m1;
        float s1 = gamma2[k1] * rsqrtf(v1 + BN_EPS);
        float t1 = beta2[k1] - m1 * s1;
        scs2[tid] = __floats2half2_rn(s0, s1);
        shs2[tid] = __floats2half2_rn(t0, t1);
    }

    // resident B panel: g_W2h (128 n x 128 words)
#pragma unroll
    for (int i = 0; i < 16; i++) {
        int idx = i * 256 + tid;
        int nrow = idx >> 5, blk = idx & 31;
        int chk = blk >> 2, j = blk & 3;
        uint32_t dw = B_OFF_W + chk * B_CHK_W + nrow * 16 + ((4 * j) ^ ((nrow & 6) << 1));
        cp16(sbase + dw * 4, &g_W2h[(size_t)nrow * 128 + blk * 4], true);
    }

    auto issueA = [&](int L) {
        int c = L & 7;
        int trow = (by + (L >> 3) * bstride) * 256;
        uint32_t abase = sbase + ((L % 3) * A_STG_W) * 4;
#pragma unroll
        for (int i = 0; i < 4; i++) {
            int idx = i * 256 + tid, row = idx >> 2, j = idx & 3;
            bool p = (trow + row) < M;
            uint32_t dw = row * 16 + ((4 * j) ^ ((row & 6) << 1));
            cp16(abase + dw * 4, &g_h16[(size_t)(trow + row) * 128 + c * 16 + 4 * j], p);
        }
    };

    issueA(0); CP_COMMIT();
    issueA(1); CP_COMMIT();
    issueA(2); CP_COMMIT();

    float d[4][8][4];
#pragma unroll
    for (int mt = 0; mt < 4; mt++)
#pragma unroll
        for (int nt = 0; nt < 8; nt++)
#pragma unroll
            for (int q = 0; q < 4; q++) d[mt][nt][q] = 0.f;

    const int rb0 = warp_m * 64 + grp;
    const int nb0 = warp_n * 64 + grp;
    const __half2 zero2 = __floats2half2_rn(0.f, 0.f);

    for (int L = 0; L < total_chunks; L++) {
        CP_WAIT2();
        __syncthreads();
        const uint32_t* As = sm + (L % 3) * A_STG_W;
        const uint32_t* Bs = sm + B_OFF_W + (L & 7) * B_CHK_W;
        const int c = L & 7;
#pragma unroll
        for (int s = 0; s < 2; s++) {
            const int w0 = s * 8 + tig, w1 = w0 + 4;
            const int kp0 = c * 16 + w0, kp1 = c * 16 + w1;
            const __half2 sc0 = scs2[kp0], sh0 = shs2[kp0];
            const __half2 sc1 = scs2[kp1], sh1 = shs2[kp1];
            uint32_t a[4][4], b[8][2];
#pragma unroll
            for (int mt = 0; mt < 4; mt++) {
                int r = rb0 + mt * 16;
                int s0 = (r & 6) << 1, s1 = ((r + 8) & 6) << 1;
                __half2 h0 = *reinterpret_cast<const __half2*>(&As[r * 16 + (w0 ^ s0)]);
                __half2 h1 = *reinterpret_cast<const __half2*>(&As[(r + 8) * 16 + (w0 ^ s1)]);
                __half2 h2 = *reinterpret_cast<const __half2*>(&As[r * 16 + (w1 ^ s0)]);
                __half2 h3 = *reinterpret_cast<const __half2*>(&As[(r + 8) * 16 + (w1 ^ s1)]);
                h0 = __hmax2(__hfma2(h0, sc0, sh0), zero2);
                h1 = __hmax2(__hfma2(h1, sc0, sh0), zero2);
                h2 = __hmax2(__hfma2(h2, sc1, sh1), zero2);
                h3 = __hmax2(__hfma2(h3, sc1, sh1), zero2);
                a[mt][0] = *reinterpret_cast<uint32_t*>(&h0);
                a[mt][1] = *reinterpret_cast<uint32_t*>(&h1);
                a[mt][2] = *reinterpret_cast<uint32_t*>(&h2);
                a[mt][3] = *reinterpret_cast<uint32_t*>(&h3);
            }
#pragma unroll
            for (int nt = 0; nt < 8; nt++) {
                int nb = nb0 + nt * 8;
                int sn = (nb & 6) << 1;
                b[nt][0] = Bs[nb * 16 + (w0 ^ sn)];
                b[nt][1] = Bs[nb * 16 + (w1 ^ sn)];
            }
#pragma unroll
            for (int mt = 0; mt < 4; mt++)
#pragma unroll
                for (int nt = 0; nt < 8; nt++) mma_f16(d[mt][nt], a[mt], b[nt]);
        }
        __syncthreads();
        if (L + 3 < total_chunks) issueA(L + 3);
        CP_COMMIT();

        if ((L & 7) == 7) {
            int trow = (by + (L >> 3) * bstride) * 256;
#pragma unroll
            for (int mt = 0; mt < 4; mt++) {
                int r0 = trow + warp_m * 64 + mt * 16 + grp;
#pragma unroll
                for (int nt = 0; nt < 8; nt++) {
                    int col = warp_n * 64 + nt * 8 + tig * 2;
                    float bx = b2[col], by2 = b2[col + 1];
                    if (r0 < M)
                        *reinterpret_cast<float2*>(&out[(size_t)r0 * N_D + col]) =
                            make_float2(d[mt][nt][0] + bx, d[mt][nt][1] + by2);
                    if (r0 + 8 < M)
                        *reinterpret_cast<float2*>(&out[(size_t)(r0 + 8) * N_D + col]) =
                            make_float2(d[mt][nt][2] + bx, d[mt][nt][3] + by2);
                    d[mt][nt][0] = 0.f; d[mt][nt][1] = 0.f;
                    d[mt][nt][2] = 0.f; d[mt][nt][3] = 0.f;
                }
            }
        }
    }
}

// ---------------------------------------------------------------------------
// Launch
// ---------------------------------------------------------------------------
extern "C" void kernel_launch(void* const* d_in, const int* in_sizes, int n_in,
                              void* d_out, int out_size) {
    const float* input  = (const float*)d_in[0];
    const int*   rows   = (const int*)  d_in[1];
    const int*   cols   = (const int*)  d_in[2];
    const float* vals   = (const float*)d_in[3];
    const float* gamma1 = (const float*)d_in[4];
    const float* beta1  = (const float*)d_in[5];
    const float* W1     = (const float*)d_in[6];
    const float* b1     = (const float*)d_in[7];
    const float* gamma2 = (const float*)d_in[8];
    const float* beta2  = (const float*)d_in[9];
    const float* W2     = (const float*)d_in[10];
    const float* b2     = (const float*)d_in[11];
    float* out = (float*)d_out;

    const int n = in_sizes[0] / N_D;
    const int E = in_sizes[1];
    const float n_inv = 1.0f / (float)n;

    cudaFuncSetAttribute(k_gemm1_mma, cudaFuncAttributeMaxDynamicSharedMemorySize, G1_SMEM);
    cudaFuncSetAttribute(k_gemm2_mma, cudaFuncAttributeMaxDynamicSharedMemorySize, G2_SMEM);

    // 0: zero agg/stats + weight staging/packing
    {
        size_t n4 = (size_t)n * N_D / 4;
        k_zero_prep<<<(int)((n4 + 255) / 256), 256>>>(n4, W1, W2);
    }
    // 1: SpMM
    {
        int warps = (E + 7) / 8;
        k_spmm<<<(warps * 32 + 255) / 256, 256>>>(input, rows, cols, vals, E);
    }
    // 2: stats of x_cat + fp16 pack of x_cat
    k_stats_cat<<<512, 128>>>(input, n);
    // 3: BN1 fold -> g_W1h + b1p
    k_bnfold<<<256, 256>>>(gamma1, beta1, b1, n_inv);
    // 4: GEMM1 persistent fp16 (2 N-blocks x 74 CTAs)
    {
        dim3 grid(2, 74);
        k_gemm1_mma<<<grid, 256, G1_SMEM>>>(n);
    }
    // 5: GEMM2 persistent fp16 (1 x 148 CTAs)
    {
        dim3 grid(1, 148);
        k_gemm2_mma<<<grid, 256, G2_SMEM>>>(gamma2, beta2, b2, out, n, n_inv);
    }
}

// round 12
// speedup vs baseline: 1.2567x; 1.0523x over previous
#include <cuda_runtime.h>
#include <cuda_fp16.h>
#include <cstdint>
#include <cstddef>

#define N_D   128
#define N_H   256
#define N_CAT 256
#define BN_EPS 1e-5f
#define MAXN  100000

// ---------------------------------------------------------------------------
// Scratch
// ---------------------------------------------------------------------------
__device__ __align__(1024) float    g_agg  [(size_t)MAXN * N_D];  // 51.2 MB f32
__device__ __align__(1024) uint32_t g_xin  [(size_t)MAXN * 64];   // 25.6 MB fp16 input
__device__ __align__(1024) uint32_t g_agg16[(size_t)MAXN * 64];   // 25.6 MB fp16 agg
__device__ __align__(1024) uint32_t g_h16  [(size_t)MAXN * 128];  // 51.2 MB fp16 h
__device__ float g_stats[4 * 256];
__device__ __align__(16) uint32_t g_W1t[N_H * N_CAT];   // staged raw W1^T (f32 bits)
__device__ __align__(16) uint32_t g_W1h[N_H * 128];     // BN1-folded W1^T fp16 pairs
__device__ __align__(16) uint32_t g_W2h[N_D * 128];     // W2^T fp16 pairs
__device__ float g_b1p[N_H];

// ---------------------------------------------------------------------------
// Helpers
// ---------------------------------------------------------------------------
__device__ __forceinline__ uint32_t smem_u32(const void* p) {
    uint32_t a;
    asm("{ .reg .u64 t; cvta.to.shared.u64 t, %1; cvt.u32.u64 %0, t; }" : "=r"(a) : "l"(p));
    return a;
}
__device__ __forceinline__ void cp16(uint32_t dst, const void* src, bool pred) {
    int sz = pred ? 16 : 0;
    asm volatile("cp.async.cg.shared.global [%0], [%1], 16, %2;"
                 :: "r"(dst), "l"(src), "r"(sz) : "memory");
}
#define CP_COMMIT() asm volatile("cp.async.commit_group;" ::: "memory")
#define CP_WAIT3()  asm volatile("cp.async.wait_group 3;" ::: "memory")
__device__ __forceinline__ uint32_t packh2(float x, float y) {
    __half2 h = __floats2half2_rn(x, y);
    return *reinterpret_cast<uint32_t*>(&h);
}
__device__ __forceinline__ void mma_f16(float d[4], const uint32_t a[4],
                                        const uint32_t b[2]) {
    asm volatile(
        "mma.sync.aligned.m16n8k16.row.col.f32.f16.f16.f32 "
        "{%0,%1,%2,%3}, {%4,%5,%6,%7}, {%8,%9}, {%0,%1,%2,%3};"
        : "+f"(d[0]), "+f"(d[1]), "+f"(d[2]), "+f"(d[3])
        : "r"(a[0]), "r"(a[1]), "r"(a[2]), "r"(a[3]), "r"(b[0]), "r"(b[1]));
}

// ---------------------------------------------------------------------------
// Launch 0: zero agg+stats, pack input fp16, stage raw W1^T, pack W2^T fp16
// ---------------------------------------------------------------------------
__global__ void k_zero_prep(size_t n4, size_t nw, const float* __restrict__ input,
                            const float* __restrict__ W1, const float* __restrict__ W2) {
    size_t gid = (size_t)blockIdx.x * blockDim.x + threadIdx.x;
    size_t stride = (size_t)gridDim.x * blockDim.x;
    float4* p = reinterpret_cast<float4*>(g_agg);
    float4 z = make_float4(0.f, 0.f, 0.f, 0.f);
    for (size_t i = gid; i < n4; i += stride) p[i] = z;
    const float2* in2 = reinterpret_cast<const float2*>(input);
    for (size_t w = gid; w < nw; w += stride) {
        float2 v = in2[w];
        g_xin[w] = packh2(v.x, v.y);
    }
    int j = blockIdx.x, t = threadIdx.x;
    if (j == 0)
        for (int q = t; q < 4 * 256; q += blockDim.x) g_stats[q] = 0.f;
    if (j < 256) {
        g_W1t[(size_t)j * N_CAT + t] = __float_as_uint(W1[(size_t)t * N_H + j]);
    } else if (j < 384 && t < 128) {
        int n = j - 256;
        float w0 = W2[(size_t)(2 * t) * N_D + n];
        float w1 = W2[(size_t)(2 * t + 1) * N_D + n];
        g_W2h[(size_t)n * 128 + t] = packh2(w0, w1);
    }
}

// Launch 1: SpMM, 8 edges/warp, fp16 gathers (256B/edge), f32 reduction
__global__ void k_spmm(const int* __restrict__ rows, const int* __restrict__ cols,
                       const float* __restrict__ vals, int E) {
    int gw = (int)(((size_t)blockIdx.x * blockDim.x + threadIdx.x) >> 5);
    int lane = threadIdx.x & 31;
    int base = gw * 8;
    if (base >= E) return;

    int e = base + (lane & 7);
    bool ev = e < E;
    int c = ev ? cols[e] : 0;
    int r = ev ? rows[e] : 0;
    float v = ev ? vals[e] : 0.f;

    uint2 m[8];
    int ri[8];
    float vi[8];
#pragma unroll
    for (int i = 0; i < 8; i++) {
        int ci = __shfl_sync(0xffffffffu, c, i);
        ri[i]  = __shfl_sync(0xffffffffu, r, i);
        vi[i]  = __shfl_sync(0xffffffffu, v, i);
        m[i] = reinterpret_cast<const uint2*>(g_xin + (size_t)ci * 64)[lane];
    }
#pragma unroll
    for (int i = 0; i < 8; i++) {
        if (base + i < E) {
            float2 f0 = __half22float2(*reinterpret_cast<__half2*>(&m[i].x));
            float2 f1 = __half22float2(*reinterpret_cast<__half2*>(&m[i].y));
            float* dst = g_agg + (size_t)ri[i] * N_D + lane * 4;
            asm volatile("red.global.add.v4.f32 [%0], {%1,%2,%3,%4};"
                         :: "l"(dst), "f"(vi[i] * f0.x), "f"(vi[i] * f0.y),
                            "f"(vi[i] * f1.x), "f"(vi[i] * f1.y) : "memory");
        }
    }
}

// Launch 2: column stats of x_cat + pack agg half fp16. 128 thr, 2 cols each.
__global__ void k_stats_cat(int n) {
    int t = threadIdx.x;   // cols 2t, 2t+1
    float s0 = 0.f, q0 = 0.f, s1 = 0.f, q1 = 0.f;
    if (t < 64) {
        for (int r = blockIdx.x; r < n; r += gridDim.x) {
            uint32_t w = g_xin[(size_t)r * 64 + t];
            float2 v = __half22float2(*reinterpret_cast<__half2*>(&w));
            s0 += v.x; q0 += v.x * v.x;
            s1 += v.y; q1 += v.y * v.y;
        }
    } else {
        int j = t - 64;
        for (int r = blockIdx.x; r < n; r += gridDim.x) {
            float2 v = *reinterpret_cast<const float2*>(g_agg + (size_t)r * N_D + 2 * j);
            s0 += v.x; q0 += v.x * v.x;
            s1 += v.y; q1 += v.y * v.y;
            g_agg16[(size_t)r * 64 + j] = packh2(v.x, v.y);
        }
    }
    atomicAdd(&g_stats[2 * t], s0);
    atomicAdd(&g_stats[2 * t + 1], s1);
    atomicAdd(&g_stats[256 + 2 * t], q0);
    atomicAdd(&g_stats[256 + 2 * t + 1], q1);
}

// Launch 3: fold BN1 into W1 -> g_W1h fp16 pairs + b1p
__global__ void k_bnfold(const float* __restrict__ gamma1, const float* __restrict__ beta1,
                         const float* __restrict__ b1, float n_inv) {
    __shared__ float sw[256];
    __shared__ float red[256];
    int j = blockIdx.x, t = threadIdx.x;
    float mean = g_stats[t] * n_inv;
    float var  = g_stats[256 + t] * n_inv - mean * mean;
    float sc   = gamma1[t] * rsqrtf(var + BN_EPS);
    float sh   = beta1[t] - mean * sc;
    float w = __uint_as_float(g_W1t[(size_t)j * N_CAT + t]);
    sw[t] = sc * w;
    red[t] = sh * w;
    __syncthreads();
    if (t < 128) g_W1h[(size_t)j * 128 + t] = packh2(sw[2 * t], sw[2 * t + 1]);
    for (int s = 128; s > 0; s >>= 1) {
        if (t < s) red[t] += red[t + s];
        __syncthreads();
    }
    if (t == 0) g_b1p[j] = b1[j] + red[0];
}

// ---------------------------------------------------------------------------
// Persistent fp16 GEMMs, resident-B, 4-stage A pipeline.
// CTA 256 thr = 8 warps (4M x 2N), warp tile 64x64, M-tile 256, N-block 128.
// A: fp16 smem, 4 stages of 256 rows x 16 words. B: 8 chunks x 128 x 16.
// Swizzle: w' = w ^ ((row & 6) << 1).
// ---------------------------------------------------------------------------
#define A_STG_W   4096
#define B_OFF_W   16384
#define B_CHK_W   2048
#define G1_SMEM   ((B_OFF_W + 8 * B_CHK_W) * 4)            // 131072
#define G2_SMEM   ((B_OFF_W + 8 * B_CHK_W + 256) * 4)

// Launch 4: GEMM1: h = [xin|agg16] @ W1h^T + b1p ; writes g_h16; fused h-stats
__global__ __launch_bounds__(256, 1)
void k_gemm1_mma(int M) {
    extern __shared__ uint32_t sm[];
    const uint32_t sbase = smem_u32(sm);
    const int tid = threadIdx.x, wid = tid >> 5, lane = tid & 31;
    const int warp_m = wid & 3, warp_n = wid >> 2;
    const int grp = lane >> 2, tig = lane & 3;
    const int block_col = blockIdx.x * 128;
    const int by = blockIdx.y, bstride = gridDim.y;
    const int ntiles = (M + 255) / 256;
    const int total_chunks = ((ntiles - by + bstride - 1) / bstride) * 8;

    // resident B panel
#pragma unroll
    for (int i = 0; i < 16; i++) {
        int idx = i * 256 + tid;
        int nrow = idx >> 5, blk = idx & 31;
        int chk = blk >> 2, j = blk & 3;
        uint32_t dw = B_OFF_W + chk * B_CHK_W + nrow * 16 + ((4 * j) ^ ((nrow & 6) << 1));
        cp16(sbase + dw * 4, &g_W1h[(size_t)(block_col + nrow) * 128 + blk * 4], true);
    }

    auto issueA = [&](int L) {
        int c = L & 7;
        int trow = (by + (L >> 3) * bstride) * 256;
        const uint32_t* asrc = (c < 4) ? g_xin : g_agg16;
        int kw = (c & 3) * 16;
        uint32_t abase = sbase + ((L & 3) * A_STG_W) * 4;
#pragma unroll
        for (int i = 0; i < 4; i++) {
            int idx = i * 256 + tid, row = idx >> 2, j = idx & 3;
            bool p = (trow + row) < M;
            uint32_t dw = row * 16 + ((4 * j) ^ ((row & 6) << 1));
            cp16(abase + dw * 4, asrc + (size_t)(trow + row) * 64 + kw + 4 * j, p);
        }
    };

    issueA(0); CP_COMMIT();
    issueA(1); CP_COMMIT();
    issueA(2); CP_COMMIT();
    issueA(3); CP_COMMIT();

    float d[4][8][4];
#pragma unroll
    for (int mt = 0; mt < 4; mt++)
#pragma unroll
        for (int nt = 0; nt < 8; nt++)
#pragma unroll
            for (int q = 0; q < 4; q++) d[mt][nt][q] = 0.f;

    float cs[16], cq[16];
#pragma unroll
    for (int i = 0; i < 16; i++) { cs[i] = 0.f; cq[i] = 0.f; }

    const int rb0 = warp_m * 64 + grp;
    const int nb0 = warp_n * 64 + grp;

    for (int L = 0; L < total_chunks; L++) {
        CP_WAIT3();
        __syncthreads();
        const uint32_t* As = sm + (L & 3) * A_STG_W;
        const uint32_t* Bs = sm + B_OFF_W + (L & 7) * B_CHK_W;
#pragma unroll
        for (int s = 0; s < 2; s++) {
            const int w0 = s * 8 + tig, w1 = w0 + 4;
            uint32_t a[4][4], b[8][2];
#pragma unroll
            for (int mt = 0; mt < 4; mt++) {
                int r = rb0 + mt * 16;
                int s0 = (r & 6) << 1, s1 = ((r + 8) & 6) << 1;
                a[mt][0] = As[r * 16 + (w0 ^ s0)];
                a[mt][1] = As[(r + 8) * 16 + (w0 ^ s1)];
                a[mt][2] = As[r * 16 + (w1 ^ s0)];
                a[mt][3] = As[(r + 8) * 16 + (w1 ^ s1)];
            }
#pragma unroll
            for (int nt = 0; nt < 8; nt++) {
                int nb = nb0 + nt * 8;
                int sn = (nb & 6) << 1;
                b[nt][0] = Bs[nb * 16 + (w0 ^ sn)];
                b[nt][1] = Bs[nb * 16 + (w1 ^ sn)];
            }
#pragma unroll
            for (int mt = 0; mt < 4; mt++)
#pragma unroll
                for (int nt = 0; nt < 8; nt++) mma_f16(d[mt][nt], a[mt], b[nt]);
        }
        __syncthreads();
        if (L + 4 < total_chunks) issueA(L + 4);
        CP_COMMIT();

        if ((L & 7) == 7) {
            int trow = (by + (L >> 3) * bstride) * 256;
#pragma unroll
            for (int mt = 0; mt < 4; mt++) {
                int r0 = trow + warp_m * 64 + mt * 16 + grp;
#pragma unroll
                for (int nt = 0; nt < 8; nt++) {
                    int col = block_col + warp_n * 64 + nt * 8 + tig * 2;
                    float bx = g_b1p[col], by2 = g_b1p[col + 1];
                    float vx = d[mt][nt][0] + bx, vy = d[mt][nt][1] + by2;
                    float vz = d[mt][nt][2] + bx, vw = d[mt][nt][3] + by2;
                    if (r0 < M) {
                        g_h16[(size_t)r0 * 128 + (col >> 1)] = packh2(vx, vy);
                        cs[nt * 2]     += vx;  cq[nt * 2]     += vx * vx;
                        cs[nt * 2 + 1] += vy;  cq[nt * 2 + 1] += vy * vy;
                    }
                    if (r0 + 8 < M) {
                        g_h16[(size_t)(r0 + 8) * 128 + (col >> 1)] = packh2(vz, vw);
                        cs[nt * 2]     += vz;  cq[nt * 2]     += vz * vz;
                        cs[nt * 2 + 1] += vw;  cq[nt * 2 + 1] += vw * vw;
                    }
                    d[mt][nt][0] = 0.f; d[mt][nt][1] = 0.f;
                    d[mt][nt][2] = 0.f; d[mt][nt][3] = 0.f;
                }
            }
        }
    }

#pragma unroll
    for (int i = 0; i < 16; i++) {
        float s = cs[i], q = cq[i];
        s += __shfl_xor_sync(0xffffffffu, s, 4);
        s += __shfl_xor_sync(0xffffffffu, s, 8);
        s += __shfl_xor_sync(0xffffffffu, s, 16);
        q += __shfl_xor_sync(0xffffffffu, q, 4);
        q += __shfl_xor_sync(0xffffffffu, q, 8);
        q += __shfl_xor_sync(0xffffffffu, q, 16);
        if (grp == 0) {
            int col = block_col + warp_n * 64 + (i >> 1) * 8 + tig * 2 + (i & 1);
            atomicAdd(&g_stats[512 + col], s);
            atomicAdd(&g_stats[768 + col], q);
        }
    }
}

// Launch 5: GEMM2: out = relu(h*sc2+sh2) @ W2h^T + b2 ; BN2 fp16 (HFMA2)
__global__ __launch_bounds__(256, 1)
void k_gemm2_mma(const float* __restrict__ gamma2, const float* __restrict__ beta2,
                 const float* __restrict__ b2, float* __restrict__ out,
                 int M, float n_inv) {
    extern __shared__ uint32_t sm[];
    const uint32_t sbase = smem_u32(sm);
    __half2* scs2 = reinterpret_cast<__half2*>(sm + B_OFF_W + 8 * B_CHK_W);
    __half2* shs2 = scs2 + 128;
    const int tid = threadIdx.x, wid = tid >> 5, lane = tid & 31;
    const int warp_m = wid & 3, warp_n = wid >> 2;
    const int grp = lane >> 2, tig = lane & 3;
    const int by = blockIdx.y, bstride = gridDim.y;
    const int ntiles = (M + 255) / 256;
    const int total_chunks = ((ntiles - by + bstride - 1) / bstride) * 8;

    if (tid < 128) {
        int k0 = 2 * tid, k1 = k0 + 1;
        float m0 = g_stats[512 + k0] * n_inv;
        float v0 = g_stats[768 + k0] * n_inv - m0 * m0;
        float s0 = gamma2[k0] * rsqrtf(v0 + BN_EPS);
        float t0 = beta2[k0] - m0 * s0;
        float m1 = g_stats[512 + k1] * n_inv;
        float v1 = g_stats[768 + k1] * n_inv - m1 * m1;
        float s1 = gamma2[k1] * rsqrtf(v1 + BN_EPS);
        float t1 = beta2[k1] - m1 * s1;
        scs2[tid] = __floats2half2_rn(s0, s1);
        shs2[tid] = __floats2half2_rn(t0, t1);
    }

#pragma unroll
    for (int i = 0; i < 16; i++) {
        int idx = i * 256 + tid;
        int nrow = idx >> 5, blk = idx & 31;
        int chk = blk >> 2, j = blk & 3;
        uint32_t dw = B_OFF_W + chk * B_CHK_W + nrow * 16 + ((4 * j) ^ ((nrow & 6) << 1));
        cp16(sbase + dw * 4, &g_W2h[(size_t)nrow * 128 + blk * 4], true);
    }

    auto issueA = [&](int L) {
        int c = L & 7;
        int trow = (by + (L >> 3) * bstride) * 256;
        uint32_t abase = sbase + ((L & 3) * A_STG_W) * 4;
#pragma unroll
        for (int i = 0; i < 4; i++) {
            int idx = i * 256 + tid, row = idx >> 2, j = idx & 3;
            bool p = (trow + row) < M;
            uint32_t dw = row * 16 + ((4 * j) ^ ((row & 6) << 1));
            cp16(abase + dw * 4, &g_h16[(size_t)(trow + row) * 128 + c * 16 + 4 * j], p);
        }
    };

    issueA(0); CP_COMMIT();
    issueA(1); CP_COMMIT();
    issueA(2); CP_COMMIT();
    issueA(3); CP_COMMIT();

    float d[4][8][4];
#pragma unroll
    for (int mt = 0; mt < 4; mt++)
#pragma unroll
        for (int nt = 0; nt < 8; nt++)
#pragma unroll
            for (int q = 0; q < 4; q++) d[mt][nt][q] = 0.f;

    const int rb0 = warp_m * 64 + grp;
    const int nb0 = warp_n * 64 + grp;
    const __half2 zero2 = __floats2half2_rn(0.f, 0.f);

    for (int L = 0; L < total_chunks; L++) {
        CP_WAIT3();
        __syncthreads();
        const uint32_t* As = sm + (L & 3) * A_STG_W;
        const uint32_t* Bs = sm + B_OFF_W + (L & 7) * B_CHK_W;
        const int c = L & 7;
#pragma unroll
        for (int s = 0; s < 2; s++) {
            const int w0 = s * 8 + tig, w1 = w0 + 4;
            const int kp0 = c * 16 + w0, kp1 = c * 16 + w1;
            const __half2 sc0 = scs2[kp0], sh0 = shs2[kp0];
            const __half2 sc1 = scs2[kp1], sh1 = shs2[kp1];
            uint32_t a[4][4], b[8][2];
#pragma unroll
            for (int mt = 0; mt < 4; mt++) {
                int r = rb0 + mt * 16;
                int s0 = (r & 6) << 1, s1 = ((r + 8) & 6) << 1;
                __half2 h0 = *reinterpret_cast<const __half2*>(&As[r * 16 + (w0 ^ s0)]);
                __half2 h1 = *reinterpret_cast<const __half2*>(&As[(r + 8) * 16 + (w0 ^ s1)]);
                __half2 h2 = *reinterpret_cast<const __half2*>(&As[r * 16 + (w1 ^ s0)]);
                __half2 h3 = *reinterpret_cast<const __half2*>(&As[(r + 8) * 16 + (w1 ^ s1)]);
                h0 = __hmax2(__hfma2(h0, sc0, sh0), zero2);
                h1 = __hmax2(__hfma2(h1, sc0, sh0), zero2);
                h2 = __hmax2(__hfma2(h2, sc1, sh1), zero2);
                h3 = __hmax2(__hfma2(h3, sc1, sh1), zero2);
                a[mt][0] = *reinterpret_cast<uint32_t*>(&h0);
                a[mt][1] = *reinterpret_cast<uint32_t*>(&h1);
                a[mt][2] = *reinterpret_cast<uint32_t*>(&h2);
                a[mt][3] = *reinterpret_cast<uint32_t*>(&h3);
            }
#pragma unroll
            for (int nt = 0; nt < 8; nt++) {
                int nb = nb0 + nt * 8;
                int sn = (nb & 6) << 1;
                b[nt][0] = Bs[nb * 16 + (w0 ^ sn)];
                b[nt][1] = Bs[nb * 16 + (w1 ^ sn)];
            }
#pragma unroll
            for (int mt = 0; mt < 4; mt++)
#pragma unroll
                for (int nt = 0; nt < 8; nt++) mma_f16(d[mt][nt], a[mt], b[nt]);
        }
        __syncthreads();
        if (L + 4 < total_chunks) issueA(L + 4);
        CP_COMMIT();

        if ((L & 7) == 7) {
            int trow = (by + (L >> 3) * bstride) * 256;
#pragma unroll
            for (int mt = 0; mt < 4; mt++) {
                int r0 = trow + warp_m * 64 + mt * 16 + grp;
#pragma unroll
                for (int nt = 0; nt < 8; nt++) {
                    int col = warp_n * 64 + nt * 8 + tig * 2;
                    float bx = b2[col], by2 = b2[col + 1];
                    if (r0 < M)
                        *reinterpret_cast<float2*>(&out[(size_t)r0 * N_D + col]) =
                            make_float2(d[mt][nt][0] + bx, d[mt][nt][1] + by2);
                    if (r0 + 8 < M)
                        *reinterpret_cast<float2*>(&out[(size_t)(r0 + 8) * N_D + col]) =
                            make_float2(d[mt][nt][2] + bx, d[mt][nt][3] + by2);
                    d[mt][nt][0] = 0.f; d[mt][nt][1] = 0.f;
                    d[mt][nt][2] = 0.f; d[mt][nt][3] = 0.f;
                }
            }
        }
    }
}

// ---------------------------------------------------------------------------
// Launch
// ---------------------------------------------------------------------------
extern "C" void kernel_launch(void* const* d_in, const int* in_sizes, int n_in,
                              void* d_out, int out_size) {
    const float* input  = (const float*)d_in[0];
    const int*   rows   = (const int*)  d_in[1];
    const int*   cols   = (const int*)  d_in[2];
    const float* vals   = (const float*)d_in[3];
    const float* gamma1 = (const float*)d_in[4];
    const float* beta1  = (const float*)d_in[5];
    const float* W1     = (const float*)d_in[6];
    const float* b1     = (const float*)d_in[7];
    const float* gamma2 = (const float*)d_in[8];
    const float* beta2  = (const float*)d_in[9];
    const float* W2     = (const float*)d_in[10];
    const float* b2     = (const float*)d_in[11];
    float* out = (float*)d_out;

    const int n = in_sizes[0] / N_D;
    const int E = in_sizes[1];
    const float n_inv = 1.0f / (float)n;

    cudaFuncSetAttribute(k_gemm1_mma, cudaFuncAttributeMaxDynamicSharedMemorySize, G1_SMEM);
    cudaFuncSetAttribute(k_gemm2_mma, cudaFuncAttributeMaxDynamicSharedMemorySize, G2_SMEM);

    // 0: zero agg/stats + input fp16 pack + weight staging
    {
        size_t n4 = (size_t)n * N_D / 4;
        size_t nw = (size_t)n * 64;
        k_zero_prep<<<(int)((n4 + 255) / 256), 256>>>(n4, nw, input, W1, W2);
    }
    // 1: SpMM (fp16 gathers)
    {
        int warps = (E + 7) / 8;
        k_spmm<<<(warps * 32 + 255) / 256, 256>>>(rows, cols, vals, E);
    }
    // 2: stats of x_cat + agg fp16 pack
    k_stats_cat<<<512, 128>>>(n);
    // 3: BN1 fold -> g_W1h + b1p
    k_bnfold<<<256, 256>>>(gamma1, beta1, b1, n_inv);
    // 4: GEMM1 persistent fp16 (2 N-blocks x 74 CTAs)
    {
        dim3 grid(2, 74);
        k_gemm1_mma<<<grid, 256, G1_SMEM>>>(n);
    }
    // 5: GEMM2 persistent fp16 (1 x 148 CTAs)
    {
        dim3 grid(1, 148);
        k_gemm2_mma<<<grid, 256, G2_SMEM>>>(gamma2, beta2, b2, out, n, n_inv);
    }
}

// round 13
// speedup vs baseline: 1.2635x; 1.0054x over previous
#include <cuda_runtime.h>
#include <cuda_fp16.h>
#include <cstdint>
#include <cstddef>

#define N_D   128
#define N_H   256
#define N_CAT 256
#define BN_EPS 1e-5f
#define MAXN  100000

// ---------------------------------------------------------------------------
// Scratch
// ---------------------------------------------------------------------------
__device__ __align__(1024) float    g_agg  [(size_t)MAXN * N_D];  // 51.2 MB f32
__device__ __align__(1024) uint32_t g_xin  [(size_t)MAXN * 64];   // 25.6 MB fp16 input
__device__ __align__(1024) uint32_t g_agg16[(size_t)MAXN * 64];   // 25.6 MB fp16 agg
__device__ __align__(1024) uint32_t g_h16  [(size_t)MAXN * 128];  // 51.2 MB fp16 h
__device__ float g_stats[4 * 256];
__device__ __align__(16) uint32_t g_W1t[N_H * N_CAT];   // staged raw W1^T (f32 bits)
__device__ __align__(16) uint32_t g_W1h[N_H * 128];     // BN1-folded W1^T fp16 pairs
__device__ __align__(16) uint32_t g_W2h[N_D * 128];     // W2^T fp16 pairs
__device__ float g_b1p[N_H];

// ---------------------------------------------------------------------------
// Helpers
// ---------------------------------------------------------------------------
__device__ __forceinline__ uint32_t smem_u32(const void* p) {
    uint32_t a;
    asm("{ .reg .u64 t; cvta.to.shared.u64 t, %1; cvt.u32.u64 %0, t; }" : "=r"(a) : "l"(p));
    return a;
}
__device__ __forceinline__ void cp16(uint32_t dst, const void* src, bool pred) {
    int sz = pred ? 16 : 0;
    asm volatile("cp.async.cg.shared.global [%0], [%1], 16, %2;"
                 :: "r"(dst), "l"(src), "r"(sz) : "memory");
}
#define CP_COMMIT() asm volatile("cp.async.commit_group;" ::: "memory")
#define CP_WAIT1()  asm volatile("cp.async.wait_group 1;" ::: "memory")
__device__ __forceinline__ uint32_t packh2(float x, float y) {
    __half2 h = __floats2half2_rn(x, y);
    return *reinterpret_cast<uint32_t*>(&h);
}
__device__ __forceinline__ void mma_f16(float d[4], const uint32_t a[4],
                                        const uint32_t b[2]) {
    asm volatile(
        "mma.sync.aligned.m16n8k16.row.col.f32.f16.f16.f32 "
        "{%0,%1,%2,%3}, {%4,%5,%6,%7}, {%8,%9}, {%0,%1,%2,%3};"
        : "+f"(d[0]), "+f"(d[1]), "+f"(d[2]), "+f"(d[3])
        : "r"(a[0]), "r"(a[1]), "r"(a[2]), "r"(a[3]), "r"(b[0]), "r"(b[1]));
}
// swizzle of 5-bit word index within a 32-word row
__device__ __forceinline__ int swz(int row) {
    return ((row & 6) << 1) ^ ((row & 1) << 4);
}

// ---------------------------------------------------------------------------
// Launch 0: zero agg+stats, pack input fp16, stage raw W1^T, pack W2^T fp16
// ---------------------------------------------------------------------------
__global__ void k_zero_prep(size_t n4, size_t nw, const float* __restrict__ input,
                            const float* __restrict__ W1, const float* __restrict__ W2) {
    size_t gid = (size_t)blockIdx.x * blockDim.x + threadIdx.x;
    size_t stride = (size_t)gridDim.x * blockDim.x;
    float4* p = reinterpret_cast<float4*>(g_agg);
    float4 z = make_float4(0.f, 0.f, 0.f, 0.f);
    for (size_t i = gid; i < n4; i += stride) p[i] = z;
    const float2* in2 = reinterpret_cast<const float2*>(input);
    for (size_t w = gid; w < nw; w += stride) {
        float2 v = in2[w];
        g_xin[w] = packh2(v.x, v.y);
    }
    int j = blockIdx.x, t = threadIdx.x;
    if (j == 0)
        for (int q = t; q < 4 * 256; q += blockDim.x) g_stats[q] = 0.f;
    if (j < 256) {
        g_W1t[(size_t)j * N_CAT + t] = __float_as_uint(W1[(size_t)t * N_H + j]);
    } else if (j < 384 && t < 128) {
        int n = j - 256;
        float w0 = W2[(size_t)(2 * t) * N_D + n];
        float w1 = W2[(size_t)(2 * t + 1) * N_D + n];
        g_W2h[(size_t)n * 128 + t] = packh2(w0, w1);
    }
}

// Launch 1: SpMM, 8 edges/warp, fp16 gathers, f32 reduction
__global__ void k_spmm(const int* __restrict__ rows, const int* __restrict__ cols,
                       const float* __restrict__ vals, int E) {
    int gw = (int)(((size_t)blockIdx.x * blockDim.x + threadIdx.x) >> 5);
    int lane = threadIdx.x & 31;
    int base = gw * 8;
    if (base >= E) return;

    int e = base + (lane & 7);
    bool ev = e < E;
    int c = ev ? cols[e] : 0;
    int r = ev ? rows[e] : 0;
    float v = ev ? vals[e] : 0.f;

    uint2 m[8];
    int ri[8];
    float vi[8];
#pragma unroll
    for (int i = 0; i < 8; i++) {
        int ci = __shfl_sync(0xffffffffu, c, i);
        ri[i]  = __shfl_sync(0xffffffffu, r, i);
        vi[i]  = __shfl_sync(0xffffffffu, v, i);
        m[i] = reinterpret_cast<const uint2*>(g_xin + (size_t)ci * 64)[lane];
    }
#pragma unroll
    for (int i = 0; i < 8; i++) {
        if (base + i < E) {
            float2 f0 = __half22float2(*reinterpret_cast<__half2*>(&m[i].x));
            float2 f1 = __half22float2(*reinterpret_cast<__half2*>(&m[i].y));
            float* dst = g_agg + (size_t)ri[i] * N_D + lane * 4;
            asm volatile("red.global.add.v4.f32 [%0], {%1,%2,%3,%4};"
                         :: "l"(dst), "f"(vi[i] * f0.x), "f"(vi[i] * f0.y),
                            "f"(vi[i] * f1.x), "f"(vi[i] * f1.y) : "memory");
        }
    }
}

// Launch 2: column stats of x_cat + pack agg half fp16
__global__ void k_stats_cat(int n) {
    int t = threadIdx.x;
    float s0 = 0.f, q0 = 0.f, s1 = 0.f, q1 = 0.f;
    if (t < 64) {
        for (int r = blockIdx.x; r < n; r += gridDim.x) {
            uint32_t w = g_xin[(size_t)r * 64 + t];
            float2 v = __half22float2(*reinterpret_cast<__half2*>(&w));
            s0 += v.x; q0 += v.x * v.x;
            s1 += v.y; q1 += v.y * v.y;
        }
    } else {
        int j = t - 64;
        for (int r = blockIdx.x; r < n; r += gridDim.x) {
            float2 v = *reinterpret_cast<const float2*>(g_agg + (size_t)r * N_D + 2 * j);
            s0 += v.x; q0 += v.x * v.x;
            s1 += v.y; q1 += v.y * v.y;
            g_agg16[(size_t)r * 64 + j] = packh2(v.x, v.y);
        }
    }
    atomicAdd(&g_stats[2 * t], s0);
    atomicAdd(&g_stats[2 * t + 1], s1);
    atomicAdd(&g_stats[256 + 2 * t], q0);
    atomicAdd(&g_stats[256 + 2 * t + 1], q1);
}

// Launch 3: fold BN1 into W1 -> g_W1h fp16 pairs + b1p
__global__ void k_bnfold(const float* __restrict__ gamma1, const float* __restrict__ beta1,
                         const float* __restrict__ b1, float n_inv) {
    __shared__ float sw[256];
    __shared__ float red[256];
    int j = blockIdx.x, t = threadIdx.x;
    float mean = g_stats[t] * n_inv;
    float var  = g_stats[256 + t] * n_inv - mean * mean;
    float sc   = gamma1[t] * rsqrtf(var + BN_EPS);
    float sh   = beta1[t] - mean * sc;
    float w = __uint_as_float(g_W1t[(size_t)j * N_CAT + t]);
    sw[t] = sc * w;
    red[t] = sh * w;
    __syncthreads();
    if (t < 128) g_W1h[(size_t)j * 128 + t] = packh2(sw[2 * t], sw[2 * t + 1]);
    for (int s = 128; s > 0; s >>= 1) {
        if (t < s) red[t] += red[t + s];
        __syncthreads();
    }
    if (t == 0) g_b1p[j] = b1[j] + red[0];
}

// ---------------------------------------------------------------------------
// Persistent fp16 GEMMs: K=64 per pipeline iteration, one barrier per iter.
// CTA 256 thr = 8 warps (4M x 2N), warp tile 64x64, M-tile 256, N-block 128.
// A: 3 stages of 256 rows x 32 words.  B: 4 K-panels of 128 rows x 32 words.
// Word swizzle within 32-word row: pw = lw ^ ((row&6)<<1) ^ ((row&1)<<4).
// ---------------------------------------------------------------------------
#define A_STG_W   8192
#define B_OFF_W   24576
#define B_BC_W    4096
#define G1_SMEM   ((B_OFF_W + 4 * B_BC_W) * 4)             // 163840
#define G2_SMEM   ((B_OFF_W + 4 * B_BC_W + 256) * 4)

// Launch 4: GEMM1: h = [xin|agg16] @ W1h^T + b1p ; writes g_h16; fused h-stats
__global__ __launch_bounds__(256, 1)
void k_gemm1_mma(int M) {
    extern __shared__ uint32_t sm[];
    const uint32_t sbase = smem_u32(sm);
    const int tid = threadIdx.x, wid = tid >> 5, lane = tid & 31;
    const int warp_m = wid & 3, warp_n = wid >> 2;
    const int grp = lane >> 2, tig = lane & 3;
    const int block_col = blockIdx.x * 128;
    const int by = blockIdx.y, bstride = gridDim.y;
    const int ntiles = (M + 255) / 256;
    const int total_iters = ((ntiles - by + bstride - 1) / bstride) * 4;

    // resident B: 4 K-panels (g_W1h rows [block_col, block_col+128))
#pragma unroll
    for (int i = 0; i < 16; i++) {
        int idx = i * 256 + tid;             // 4096 cp16
        int bc = idx >> 10, r2 = (idx >> 3) & 127, q = idx & 7;
        uint32_t dw = B_OFF_W + bc * B_BC_W + r2 * 32 + ((4 * q) ^ swz(r2));
        cp16(sbase + dw * 4, &g_W1h[(size_t)(block_col + r2) * 128 + bc * 32 + 4 * q], true);
    }
    CP_COMMIT();

    auto issueA = [&](int I) {
        int c = I & 3;                        // K-panel 0..3
        int trow = (by + (I >> 2) * bstride) * 256;
        const uint32_t* asrc = (c < 2) ? g_xin : g_agg16;
        int kw = (c & 1) * 32;
        uint32_t abase = sbase + ((I % 3) * A_STG_W) * 4;
#pragma unroll
        for (int i = 0; i < 8; i++) {
            int idx = i * 256 + tid, row = idx >> 3, j = idx & 7;
            bool p = (trow + row) < M;
            uint32_t dw = row * 32 + ((4 * j) ^ swz(row));
            cp16(abase + dw * 4, asrc + (size_t)(trow + row) * 64 + kw + 4 * j, p);
        }
    };

    issueA(0); CP_COMMIT();
    if (total_iters > 1) issueA(1);
    CP_COMMIT();

    float d[4][8][4];
#pragma unroll
    for (int mt = 0; mt < 4; mt++)
#pragma unroll
        for (int nt = 0; nt < 8; nt++)
#pragma unroll
            for (int q = 0; q < 4; q++) d[mt][nt][q] = 0.f;

    float cs[16], cq[16];
#pragma unroll
    for (int i = 0; i < 16; i++) { cs[i] = 0.f; cq[i] = 0.f; }

    const int rb0 = warp_m * 64 + grp;
    const int nb0 = warp_n * 64 + grp;

    for (int I = 0; I < total_iters; I++) {
        CP_WAIT1();
        __syncthreads();
        if (I + 2 < total_iters) issueA(I + 2);
        CP_COMMIT();
        const uint32_t* As = sm + (I % 3) * A_STG_W;
        const uint32_t* Bs = sm + B_OFF_W + (I & 3) * B_BC_W;
#pragma unroll
        for (int cc = 0; cc < 2; cc++) {
#pragma unroll
            for (int s = 0; s < 2; s++) {
                const int lw0 = cc * 16 + s * 8 + tig, lw1 = lw0 + 4;
                uint32_t a[4][4], b[8][2];
#pragma unroll
                for (int mt = 0; mt < 4; mt++) {
                    int r = rb0 + mt * 16;
                    int z0 = swz(r), z1 = swz(r + 8);
                    a[mt][0] = As[r * 32 + (lw0 ^ z0)];
                    a[mt][1] = As[(r + 8) * 32 + (lw0 ^ z1)];
                    a[mt][2] = As[r * 32 + (lw1 ^ z0)];
                    a[mt][3] = As[(r + 8) * 32 + (lw1 ^ z1)];
                }
#pragma unroll
                for (int nt = 0; nt < 8; nt++) {
                    int nb = nb0 + nt * 8;
                    int zn = swz(nb);
                    b[nt][0] = Bs[nb * 32 + (lw0 ^ zn)];
                    b[nt][1] = Bs[nb * 32 + (lw1 ^ zn)];
                }
#pragma unroll
                for (int mt = 0; mt < 4; mt++)
#pragma unroll
                    for (int nt = 0; nt < 8; nt++) mma_f16(d[mt][nt], a[mt], b[nt]);
            }
        }

        if ((I & 3) == 3) {
            int trow = (by + (I >> 2) * bstride) * 256;
#pragma unroll
            for (int mt = 0; mt < 4; mt++) {
                int r0 = trow + warp_m * 64 + mt * 16 + grp;
#pragma unroll
                for (int nt = 0; nt < 8; nt++) {
                    int col = block_col + warp_n * 64 + nt * 8 + tig * 2;
                    float bx = g_b1p[col], by2 = g_b1p[col + 1];
                    float vx = d[mt][nt][0] + bx, vy = d[mt][nt][1] + by2;
                    float vz = d[mt][nt][2] + bx, vw = d[mt][nt][3] + by2;
                    if (r0 < M) {
                        g_h16[(size_t)r0 * 128 + (col >> 1)] = packh2(vx, vy);
                        cs[nt * 2]     += vx;  cq[nt * 2]     += vx * vx;
                        cs[nt * 2 + 1] += vy;  cq[nt * 2 + 1] += vy * vy;
                    }
                    if (r0 + 8 < M) {
                        g_h16[(size_t)(r0 + 8) * 128 + (col >> 1)] = packh2(vz, vw);
                        cs[nt * 2]     += vz;  cq[nt * 2]     += vz * vz;
                        cs[nt * 2 + 1] += vw;  cq[nt * 2 + 1] += vw * vw;
                    }
                    d[mt][nt][0] = 0.f; d[mt][nt][1] = 0.f;
                    d[mt][nt][2] = 0.f; d[mt][nt][3] = 0.f;
                }
            }
        }
    }

#pragma unroll
    for (int i = 0; i < 16; i++) {
        float s = cs[i], q = cq[i];
        s += __shfl_xor_sync(0xffffffffu, s, 4);
        s += __shfl_xor_sync(0xffffffffu, s, 8);
        s += __shfl_xor_sync(0xffffffffu, s, 16);
        q += __shfl_xor_sync(0xffffffffu, q, 4);
        q += __shfl_xor_sync(0xffffffffu, q, 8);
        q += __shfl_xor_sync(0xffffffffu, q, 16);
        if (grp == 0) {
            int col = block_col + warp_n * 64 + (i >> 1) * 8 + tig * 2 + (i & 1);
            atomicAdd(&g_stats[512 + col], s);
            atomicAdd(&g_stats[768 + col], q);
        }
    }
}

// Launch 5: GEMM2: out = relu(h*sc2+sh2) @ W2h^T + b2 ; BN2 fp16 (HFMA2)
__global__ __launch_bounds__(256, 1)
void k_gemm2_mma(const float* __restrict__ gamma2, const float* __restrict__ beta2,
                 const float* __restrict__ b2, float* __restrict__ out,
                 int M, float n_inv) {
    extern __shared__ uint32_t sm[];
    const uint32_t sbase = smem_u32(sm);
    __half2* scs2 = reinterpret_cast<__half2*>(sm + B_OFF_W + 4 * B_BC_W);
    __half2* shs2 = scs2 + 128;
    const int tid = threadIdx.x, wid = tid >> 5, lane = tid & 31;
    const int warp_m = wid & 3, warp_n = wid >> 2;
    const int grp = lane >> 2, tig = lane & 3;
    const int by = blockIdx.y, bstride = gridDim.y;
    const int ntiles = (M + 255) / 256;
    const int total_iters = ((ntiles - by + bstride - 1) / bstride) * 4;

    if (tid < 128) {
        int k0 = 2 * tid, k1 = k0 + 1;
        float m0 = g_stats[512 + k0] * n_inv;
        float v0 = g_stats[768 + k0] * n_inv - m0 * m0;
        float s0 = gamma2[k0] * rsqrtf(v0 + BN_EPS);
        float t0 = beta2[k0] - m0 * s0;
        float m1 = g_stats[512 + k1] * n_inv;
        float v1 = g_stats[768 + k1] * n_inv - m1 * m1;
        float s1 = gamma2[k1] * rsqrtf(v1 + BN_EPS);
        float t1 = beta2[k1] - m1 * s1;
        scs2[tid] = __floats2half2_rn(s0, s1);
        shs2[tid] = __floats2half2_rn(t0, t1);
    }

#pragma unroll
    for (int i = 0; i < 16; i++) {
        int idx = i * 256 + tid;
        int bc = idx >> 10, r2 = (idx >> 3) & 127, q = idx & 7;
        uint32_t dw = B_OFF_W + bc * B_BC_W + r2 * 32 + ((4 * q) ^ swz(r2));
        cp16(sbase + dw * 4, &g_W2h[(size_t)r2 * 128 + bc * 32 + 4 * q], true);
    }
    CP_COMMIT();

    auto issueA = [&](int I) {
        int c = I & 3;
        int trow = (by + (I >> 2) * bstride) * 256;
        uint32_t abase = sbase + ((I % 3) * A_STG_W) * 4;
#pragma unroll
        for (int i = 0; i < 8; i++) {
            int idx = i * 256 + tid, row = idx >> 3, j = idx & 7;
            bool p = (trow + row) < M;
            uint32_t dw = row * 32 + ((4 * j) ^ swz(row));
            cp16(abase + dw * 4, &g_h16[(size_t)(trow + row) * 128 + c * 32 + 4 * j], p);
        }
    };

    issueA(0); CP_COMMIT();
    if (total_iters > 1) issueA(1);
    CP_COMMIT();

    float d[4][8][4];
#pragma unroll
    for (int mt = 0; mt < 4; mt++)
#pragma unroll
        for (int nt = 0; nt < 8; nt++)
#pragma unroll
            for (int q = 0; q < 4; q++) d[mt][nt][q] = 0.f;

    const int rb0 = warp_m * 64 + grp;
    const int nb0 = warp_n * 64 + grp;
    const __half2 zero2 = __floats2half2_rn(0.f, 0.f);

    for (int I = 0; I < total_iters; I++) {
        CP_WAIT1();
        __syncthreads();
        if (I + 2 < total_iters) issueA(I + 2);
        CP_COMMIT();
        const uint32_t* As = sm + (I % 3) * A_STG_W;
        const uint32_t* Bs = sm + B_OFF_W + (I & 3) * B_BC_W;
        const int c = I & 3;
#pragma unroll
        for (int cc = 0; cc < 2; cc++) {
#pragma unroll
            for (int s = 0; s < 2; s++) {
                const int lw0 = cc * 16 + s * 8 + tig, lw1 = lw0 + 4;
                const int kp0 = c * 32 + lw0, kp1 = c * 32 + lw1;
                const __half2 sc0 = scs2[kp0], sh0 = shs2[kp0];
                const __half2 sc1 = scs2[kp1], sh1 = shs2[kp1];
                uint32_t a[4][4], b[8][2];
#pragma unroll
                for (int mt = 0; mt < 4; mt++) {
                    int r = rb0 + mt * 16;
                    int z0 = swz(r), z1 = swz(r + 8);
                    __half2 h0 = *reinterpret_cast<const __half2*>(&As[r * 32 + (lw0 ^ z0)]);
                    __half2 h1 = *reinterpret_cast<const __half2*>(&As[(r + 8) * 32 + (lw0 ^ z1)]);
                    __half2 h2 = *reinterpret_cast<const __half2*>(&As[r * 32 + (lw1 ^ z0)]);
                    __half2 h3 = *reinterpret_cast<const __half2*>(&As[(r + 8) * 32 + (lw1 ^ z1)]);
                    h0 = __hmax2(__hfma2(h0, sc0, sh0), zero2);
                    h1 = __hmax2(__hfma2(h1, sc0, sh0), zero2);
                    h2 = __hmax2(__hfma2(h2, sc1, sh1), zero2);
                    h3 = __hmax2(__hfma2(h3, sc1, sh1), zero2);
                    a[mt][0] = *reinterpret_cast<uint32_t*>(&h0);
                    a[mt][1] = *reinterpret_cast<uint32_t*>(&h1);
                    a[mt][2] = *reinterpret_cast<uint32_t*>(&h2);
                    a[mt][3] = *reinterpret_cast<uint32_t*>(&h3);
                }
#pragma unroll
                for (int nt = 0; nt < 8; nt++) {
                    int nb = nb0 + nt * 8;
                    int zn = swz(nb);
                    b[nt][0] = Bs[nb * 32 + (lw0 ^ zn)];
                    b[nt][1] = Bs[nb * 32 + (lw1 ^ zn)];
                }
#pragma unroll
                for (int mt = 0; mt < 4; mt++)
#pragma unroll
                    for (int nt = 0; nt < 8; nt++) mma_f16(d[mt][nt], a[mt], b[nt]);
            }
        }

        if ((I & 3) == 3) {
            int trow = (by + (I >> 2) * bstride) * 256;
#pragma unroll
            for (int mt = 0; mt < 4; mt++) {
                int r0 = trow + warp_m * 64 + mt * 16 + grp;
#pragma unroll
                for (int nt = 0; nt < 8; nt++) {
                    int col = warp_n * 64 + nt * 8 + tig * 2;
                    float bx = b2[col], by2 = b2[col + 1];
                    if (r0 < M)
                        *reinterpret_cast<float2*>(&out[(size_t)r0 * N_D + col]) =
                            make_float2(d[mt][nt][0] + bx, d[mt][nt][1] + by2);
                    if (r0 + 8 < M)
                        *reinterpret_cast<float2*>(&out[(size_t)(r0 + 8) * N_D + col]) =
                            make_float2(d[mt][nt][2] + bx, d[mt][nt][3] + by2);
                    d[mt][nt][0] = 0.f; d[mt][nt][1] = 0.f;
                    d[mt][nt][2] = 0.f; d[mt][nt][3] = 0.f;
                }
            }
        }
    }
}

// ---------------------------------------------------------------------------
// Launch
// ---------------------------------------------------------------------------
extern "C" void kernel_launch(void* const* d_in, const int* in_sizes, int n_in,
                              void* d_out, int out_size) {
    const float* input  = (const float*)d_in[0];
    const int*   rows   = (const int*)  d_in[1];
    const int*   cols   = (const int*)  d_in[2];
    const float* vals   = (const float*)d_in[3];
    const float* gamma1 = (const float*)d_in[4];
    const float* beta1  = (const float*)d_in[5];
    const float* W1     = (const float*)d_in[6];
    const float* b1     = (const float*)d_in[7];
    const float* gamma2 = (const float*)d_in[8];
    const float* beta2  = (const float*)d_in[9];
    const float* W2     = (const float*)d_in[10];
    const float* b2     = (const float*)d_in[11];
    float* out = (float*)d_out;

    const int n = in_sizes[0] / N_D;
    const int E = in_sizes[1];
    const float n_inv = 1.0f / (float)n;

    cudaFuncSetAttribute(k_gemm1_mma, cudaFuncAttributeMaxDynamicSharedMemorySize, G1_SMEM);
    cudaFuncSetAttribute(k_gemm2_mma, cudaFuncAttributeMaxDynamicSharedMemorySize, G2_SMEM);

    // 0: zero agg/stats + input fp16 pack + weight staging
    {
        size_t n4 = (size_t)n * N_D / 4;
        size_t nw = (size_t)n * 64;
        k_zero_prep<<<(int)((n4 + 255) / 256), 256>>>(n4, nw, input, W1, W2);
    }
    // 1: SpMM (fp16 gathers)
    {
        int warps = (E + 7) / 8;
        k_spmm<<<(warps * 32 + 255) / 256, 256>>>(rows, cols, vals, E);
    }
    // 2: stats of x_cat + agg fp16 pack
    k_stats_cat<<<512, 128>>>(n);
    // 3: BN1 fold -> g_W1h + b1p
    k_bnfold<<<256, 256>>>(gamma1, beta1, b1, n_inv);
    // 4: GEMM1 persistent fp16, K=64/iter (2 N-blocks x 74 CTAs)
    {
        dim3 grid(2, 74);
        k_gemm1_mma<<<grid, 256, G1_SMEM>>>(n);
    }
    // 5: GEMM2 persistent fp16, K=64/iter (1 x 148 CTAs)
    {
        dim3 grid(1, 148);
        k_gemm2_mma<<<grid, 256, G2_SMEM>>>(gamma2, beta2, b2, out, n, n_inv);
    }
}

// round 14
// speedup vs baseline: 1.2659x; 1.0019x over previous
#include <cuda_runtime.h>
#include <cuda_fp16.h>
#include <cstdint>
#include <cstddef>

#define N_D   128
#define N_H   256
#define N_CAT 256
#define BN_EPS 1e-5f
#define MAXN  100000

// ---------------------------------------------------------------------------
// Scratch
// ---------------------------------------------------------------------------
__device__ __align__(1024) float    g_agg  [(size_t)MAXN * N_D];  // 51.2 MB f32
__device__ __align__(1024) uint32_t g_xin  [(size_t)MAXN * 64];   // 25.6 MB fp16 input
__device__ __align__(1024) uint32_t g_agg16[(size_t)MAXN * 64];   // 25.6 MB fp16 agg
__device__ __align__(1024) uint32_t g_h16  [(size_t)MAXN * 128];  // 51.2 MB fp16 h
__device__ float g_stats[4 * 256];
__device__ __align__(16) uint32_t g_W1t[N_H * N_CAT];   // raw W1^T (f32 bits)
__device__ __align__(16) uint32_t g_W2h[N_D * 128];     // W2^T fp16 pairs

// ---------------------------------------------------------------------------
// Helpers
// ---------------------------------------------------------------------------
__device__ __forceinline__ uint32_t smem_u32(const void* p) {
    uint32_t a;
    asm("{ .reg .u64 t; cvta.to.shared.u64 t, %1; cvt.u32.u64 %0, t; }" : "=r"(a) : "l"(p));
    return a;
}
__device__ __forceinline__ void cp16(uint32_t dst, const void* src, bool pred) {
    int sz = pred ? 16 : 0;
    asm volatile("cp.async.cg.shared.global [%0], [%1], 16, %2;"
                 :: "r"(dst), "l"(src), "r"(sz) : "memory");
}
#define CP_COMMIT() asm volatile("cp.async.commit_group;" ::: "memory")
#define CP_WAIT1()  asm volatile("cp.async.wait_group 1;" ::: "memory")
__device__ __forceinline__ uint32_t packh2(float x, float y) {
    __half2 h = __floats2half2_rn(x, y);
    return *reinterpret_cast<uint32_t*>(&h);
}
__device__ __forceinline__ void mma_f16(float d[4], const uint32_t a[4],
                                        const uint32_t b[2]) {
    asm volatile(
        "mma.sync.aligned.m16n8k16.row.col.f32.f16.f16.f32 "
        "{%0,%1,%2,%3}, {%4,%5,%6,%7}, {%8,%9}, {%0,%1,%2,%3};"
        : "+f"(d[0]), "+f"(d[1]), "+f"(d[2]), "+f"(d[3])
        : "r"(a[0]), "r"(a[1]), "r"(a[2]), "r"(a[3]), "r"(b[0]), "r"(b[1]));
}
__device__ __forceinline__ int swz(int row) {
    return ((row & 6) << 1) ^ ((row & 1) << 4);
}

// ---------------------------------------------------------------------------
// Launch 0: zero agg+stats, pack input fp16, stage raw W1^T, pack W2^T fp16
// ---------------------------------------------------------------------------
__global__ void k_zero_prep(size_t n4, size_t nw, const float* __restrict__ input,
                            const float* __restrict__ W1, const float* __restrict__ W2) {
    size_t gid = (size_t)blockIdx.x * blockDim.x + threadIdx.x;
    size_t stride = (size_t)gridDim.x * blockDim.x;
    float4* p = reinterpret_cast<float4*>(g_agg);
    float4 z = make_float4(0.f, 0.f, 0.f, 0.f);
    for (size_t i = gid; i < n4; i += stride) p[i] = z;
    const float2* in2 = reinterpret_cast<const float2*>(input);
    for (size_t w = gid; w < nw; w += stride) {
        float2 v = in2[w];
        g_xin[w] = packh2(v.x, v.y);
    }
    int j = blockIdx.x, t = threadIdx.x;
    if (j == 0)
        for (int q = t; q < 4 * 256; q += blockDim.x) g_stats[q] = 0.f;
    if (j < 256) {
        g_W1t[(size_t)j * N_CAT + t] = __float_as_uint(W1[(size_t)t * N_H + j]);
    } else if (j < 384 && t < 128) {
        int n = j - 256;
        float w0 = W2[(size_t)(2 * t) * N_D + n];
        float w1 = W2[(size_t)(2 * t + 1) * N_D + n];
        g_W2h[(size_t)n * 128 + t] = packh2(w0, w1);
    }
}

// Launch 1: SpMM, 8 edges/warp, fp16 gathers, f32 reduction
__global__ void k_spmm(const int* __restrict__ rows, const int* __restrict__ cols,
                       const float* __restrict__ vals, int E) {
    int gw = (int)(((size_t)blockIdx.x * blockDim.x + threadIdx.x) >> 5);
    int lane = threadIdx.x & 31;
    int base = gw * 8;
    if (base >= E) return;

    int e = base + (lane & 7);
    bool ev = e < E;
    int c = ev ? cols[e] : 0;
    int r = ev ? rows[e] : 0;
    float v = ev ? vals[e] : 0.f;

    uint2 m[8];
    int ri[8];
    float vi[8];
#pragma unroll
    for (int i = 0; i < 8; i++) {
        int ci = __shfl_sync(0xffffffffu, c, i);
        ri[i]  = __shfl_sync(0xffffffffu, r, i);
        vi[i]  = __shfl_sync(0xffffffffu, v, i);
        m[i] = reinterpret_cast<const uint2*>(g_xin + (size_t)ci * 64)[lane];
    }
#pragma unroll
    for (int i = 0; i < 8; i++) {
        if (base + i < E) {
            float2 f0 = __half22float2(*reinterpret_cast<__half2*>(&m[i].x));
            float2 f1 = __half22float2(*reinterpret_cast<__half2*>(&m[i].y));
            float* dst = g_agg + (size_t)ri[i] * N_D + lane * 4;
            asm volatile("red.global.add.v4.f32 [%0], {%1,%2,%3,%4};"
                         :: "l"(dst), "f"(vi[i] * f0.x), "f"(vi[i] * f0.y),
                            "f"(vi[i] * f1.x), "f"(vi[i] * f1.y) : "memory");
        }
    }
}

// Launch 2: column stats of x_cat + pack agg half fp16
__global__ void k_stats_cat(int n) {
    int t = threadIdx.x;
    float s0 = 0.f, q0 = 0.f, s1 = 0.f, q1 = 0.f;
    if (t < 64) {
        for (int r = blockIdx.x; r < n; r += gridDim.x) {
            uint32_t w = g_xin[(size_t)r * 64 + t];
            float2 v = __half22float2(*reinterpret_cast<__half2*>(&w));
            s0 += v.x; q0 += v.x * v.x;
            s1 += v.y; q1 += v.y * v.y;
        }
    } else {
        int j = t - 64;
        for (int r = blockIdx.x; r < n; r += gridDim.x) {
            float2 v = *reinterpret_cast<const float2*>(g_agg + (size_t)r * N_D + 2 * j);
            s0 += v.x; q0 += v.x * v.x;
            s1 += v.y; q1 += v.y * v.y;
            g_agg16[(size_t)r * 64 + j] = packh2(v.x, v.y);
        }
    }
    atomicAdd(&g_stats[2 * t], s0);
    atomicAdd(&g_stats[2 * t + 1], s1);
    atomicAdd(&g_stats[256 + 2 * t], q0);
    atomicAdd(&g_stats[256 + 2 * t + 1], q1);
}

// ---------------------------------------------------------------------------
// Persistent fp16 GEMMs: K=64/iter, 1 barrier/iter, resident B.
// CTA 256 thr = 8 warps (4M x 2N), warp tile 64x64, M-tile 256, N-block 128.
// A: 3 stages x 256 rows x 32 words.  B: 4 K-panels x 128 rows x 32 words.
// Word swizzle: lw ^ ((row&6)<<1) ^ ((row&1)<<4).
// ---------------------------------------------------------------------------
#define A_STG_W   8192
#define B_OFF_W   24576
#define B_BC_W    4096
#define EXTRA_W   (B_OFF_W + 4 * B_BC_W)       // 40960
#define G1_SMEM   ((EXTRA_W + 512 + 128) * 4)  // + scs1/shs1 + b1ps
#define G2_SMEM   ((EXTRA_W + 256) * 4)        // + scs2/shs2 half2

// Launch 3 (PROFILED): GEMM1 with in-kernel BN1 fold of the B panel.
__global__ __launch_bounds__(256, 1)
void k_gemm1_mma(const float* __restrict__ gamma1, const float* __restrict__ beta1,
                 const float* __restrict__ b1, int M, float n_inv) {
    extern __shared__ uint32_t sm[];
    const uint32_t sbase = smem_u32(sm);
    float* scs1 = reinterpret_cast<float*>(sm + EXTRA_W);
    float* shs1 = scs1 + 256;
    float* b1ps = shs1 + 256;
    const int tid = threadIdx.x, wid = tid >> 5, lane = tid & 31;
    const int warp_m = wid & 3, warp_n = wid >> 2;
    const int grp = lane >> 2, tig = lane & 3;
    const int block_col = blockIdx.x * 128;
    const int by = blockIdx.y, bstride = gridDim.y;
    const int ntiles = (M + 255) / 256;
    const int total_iters = ((ntiles - by + bstride - 1) / bstride) * 4;

    auto issueA = [&](int I) {
        int c = I & 3;
        int trow = (by + (I >> 2) * bstride) * 256;
        const uint32_t* asrc = (c < 2) ? g_xin : g_agg16;
        int kw = (c & 1) * 32;
        uint32_t abase = sbase + ((I % 3) * A_STG_W) * 4;
#pragma unroll
        for (int i = 0; i < 8; i++) {
            int idx = i * 256 + tid, row = idx >> 3, j = idx & 7;
            bool p = (trow + row) < M;
            uint32_t dw = row * 32 + ((4 * j) ^ swz(row));
            cp16(abase + dw * 4, asrc + (size_t)(trow + row) * 64 + kw + 4 * j, p);
        }
    };

    // Prefetch first two A chunks while we fold B.
    issueA(0); CP_COMMIT();
    if (total_iters > 1) issueA(1);
    CP_COMMIT();

    // BN1 params from stats
    {
        float mean = g_stats[tid] * n_inv;
        float var  = g_stats[256 + tid] * n_inv - mean * mean;
        float sc   = gamma1[tid] * rsqrtf(var + BN_EPS);
        scs1[tid] = sc;
        shs1[tid] = beta1[tid] - mean * sc;
    }
    __syncthreads();

    // Fold B panel: thread pair (2 per n-row) covers K=256; pack fp16 to smem;
    // accumulate b1p = b1 + sum_k sh[k]*W1[k][j].
    {
        int nrow = tid >> 1, half = tid & 1;
        int zn = swz(nrow);
        float bs = 0.f;
        const uint32_t* wrow = g_W1t + (size_t)(block_col + nrow) * N_CAT + half * 128;
#pragma unroll
        for (int i = 0; i < 32; i++) {
            int k = half * 128 + i * 4;
            float4 w4 = *reinterpret_cast<const float4*>(wrow + i * 4);
            uint32_t p0 = packh2(scs1[k] * w4.x, scs1[k + 1] * w4.y);
            uint32_t p1 = packh2(scs1[k + 2] * w4.z, scs1[k + 3] * w4.w);
            bs += shs1[k] * w4.x + shs1[k + 1] * w4.y
                + shs1[k + 2] * w4.z + shs1[k + 3] * w4.w;
            int bc = k >> 6, lw = (k & 63) >> 1;
            uint32_t base = B_OFF_W + bc * B_BC_W + nrow * 32 + (lw ^ zn);
            *reinterpret_cast<uint2*>(&sm[base]) = make_uint2(p0, p1);
        }
        bs += __shfl_xor_sync(0xffffffffu, bs, 1);
        if (half == 0) b1ps[nrow] = b1[block_col + nrow] + bs;
    }

    float d[4][8][4];
#pragma unroll
    for (int mt = 0; mt < 4; mt++)
#pragma unroll
        for (int nt = 0; nt < 8; nt++)
#pragma unroll
            for (int q = 0; q < 4; q++) d[mt][nt][q] = 0.f;

    float cs[16], cq[16];
#pragma unroll
    for (int i = 0; i < 16; i++) { cs[i] = 0.f; cq[i] = 0.f; }

    const int rb0 = warp_m * 64 + grp;
    const int nb0 = warp_n * 64 + grp;

    __syncthreads();   // B fold + b1ps visible

    for (int I = 0; I < total_iters; I++) {
        CP_WAIT1();
        __syncthreads();
        if (I + 2 < total_iters) issueA(I + 2);
        CP_COMMIT();
        const uint32_t* As = sm + (I % 3) * A_STG_W;
        const uint32_t* Bs = sm + B_OFF_W + (I & 3) * B_BC_W;
#pragma unroll
        for (int cc = 0; cc < 2; cc++) {
#pragma unroll
            for (int s = 0; s < 2; s++) {
                const int lw0 = cc * 16 + s * 8 + tig, lw1 = lw0 + 4;
                uint32_t a[4][4], b[8][2];
#pragma unroll
                for (int mt = 0; mt < 4; mt++) {
                    int r = rb0 + mt * 16;
                    int z0 = swz(r), z1 = swz(r + 8);
                    a[mt][0] = As[r * 32 + (lw0 ^ z0)];
                    a[mt][1] = As[(r + 8) * 32 + (lw0 ^ z1)];
                    a[mt][2] = As[r * 32 + (lw1 ^ z0)];
                    a[mt][3] = As[(r + 8) * 32 + (lw1 ^ z1)];
                }
#pragma unroll
                for (int nt = 0; nt < 8; nt++) {
                    int nb = nb0 + nt * 8;
                    int zn = swz(nb);
                    b[nt][0] = Bs[nb * 32 + (lw0 ^ zn)];
                    b[nt][1] = Bs[nb * 32 + (lw1 ^ zn)];
                }
#pragma unroll
                for (int mt = 0; mt < 4; mt++)
#pragma unroll
                    for (int nt = 0; nt < 8; nt++) mma_f16(d[mt][nt], a[mt], b[nt]);
            }
        }

        if ((I & 3) == 3) {
            int trow = (by + (I >> 2) * bstride) * 256;
#pragma unroll
            for (int mt = 0; mt < 4; mt++) {
                int r0 = trow + warp_m * 64 + mt * 16 + grp;
#pragma unroll
                for (int nt = 0; nt < 8; nt++) {
                    int lcol = warp_n * 64 + nt * 8 + tig * 2;
                    int col = block_col + lcol;
                    float bx = b1ps[lcol], by2 = b1ps[lcol + 1];
                    float vx = d[mt][nt][0] + bx, vy = d[mt][nt][1] + by2;
                    float vz = d[mt][nt][2] + bx, vw = d[mt][nt][3] + by2;
                    if (r0 < M) {
                        g_h16[(size_t)r0 * 128 + (col >> 1)] = packh2(vx, vy);
                        cs[nt * 2]     += vx;  cq[nt * 2]     += vx * vx;
                        cs[nt * 2 + 1] += vy;  cq[nt * 2 + 1] += vy * vy;
                    }
                    if (r0 + 8 < M) {
                        g_h16[(size_t)(r0 + 8) * 128 + (col >> 1)] = packh2(vz, vw);
                        cs[nt * 2]     += vz;  cq[nt * 2]     += vz * vz;
                        cs[nt * 2 + 1] += vw;  cq[nt * 2 + 1] += vw * vw;
                    }
                    d[mt][nt][0] = 0.f; d[mt][nt][1] = 0.f;
                    d[mt][nt][2] = 0.f; d[mt][nt][3] = 0.f;
                }
            }
        }
    }

#pragma unroll
    for (int i = 0; i < 16; i++) {
        float s = cs[i], q = cq[i];
        s += __shfl_xor_sync(0xffffffffu, s, 4);
        s += __shfl_xor_sync(0xffffffffu, s, 8);
        s += __shfl_xor_sync(0xffffffffu, s, 16);
        q += __shfl_xor_sync(0xffffffffu, q, 4);
        q += __shfl_xor_sync(0xffffffffu, q, 8);
        q += __shfl_xor_sync(0xffffffffu, q, 16);
        if (grp == 0) {
            int col = block_col + warp_n * 64 + (i >> 1) * 8 + tig * 2 + (i & 1);
            atomicAdd(&g_stats[512 + col], s);
            atomicAdd(&g_stats[768 + col], q);
        }
    }
}

// Launch 4: GEMM2: out = relu(h*sc2+sh2) @ W2h^T + b2 ; BN2 fp16 (HFMA2)
__global__ __launch_bounds__(256, 1)
void k_gemm2_mma(const float* __restrict__ gamma2, const float* __restrict__ beta2,
                 const float* __restrict__ b2, float* __restrict__ out,
                 int M, float n_inv) {
    extern __shared__ uint32_t sm[];
    const uint32_t sbase = smem_u32(sm);
    __half2* scs2 = reinterpret_cast<__half2*>(sm + EXTRA_W);
    __half2* shs2 = scs2 + 128;
    const int tid = threadIdx.x, wid = tid >> 5, lane = tid & 31;
    const int warp_m = wid & 3, warp_n = wid >> 2;
    const int grp = lane >> 2, tig = lane & 3;
    const int by = blockIdx.y, bstride = gridDim.y;
    const int ntiles = (M + 255) / 256;
    const int total_iters = ((ntiles - by + bstride - 1) / bstride) * 4;

    if (tid < 128) {
        int k0 = 2 * tid, k1 = k0 + 1;
        float m0 = g_stats[512 + k0] * n_inv;
        float v0 = g_stats[768 + k0] * n_inv - m0 * m0;
        float s0 = gamma2[k0] * rsqrtf(v0 + BN_EPS);
        float t0 = beta2[k0] - m0 * s0;
        float m1 = g_stats[512 + k1] * n_inv;
        float v1 = g_stats[768 + k1] * n_inv - m1 * m1;
        float s1 = gamma2[k1] * rsqrtf(v1 + BN_EPS);
        float t1 = beta2[k1] - m1 * s1;
        scs2[tid] = __floats2half2_rn(s0, s1);
        shs2[tid] = __floats2half2_rn(t0, t1);
    }

#pragma unroll
    for (int i = 0; i < 16; i++) {
        int idx = i * 256 + tid;
        int bc = idx >> 10, r2 = (idx >> 3) & 127, q = idx & 7;
        uint32_t dw = B_OFF_W + bc * B_BC_W + r2 * 32 + ((4 * q) ^ swz(r2));
        cp16(sbase + dw * 4, &g_W2h[(size_t)r2 * 128 + bc * 32 + 4 * q], true);
    }
    CP_COMMIT();

    auto issueA = [&](int I) {
        int c = I & 3;
        int trow = (by + (I >> 2) * bstride) * 256;
        uint32_t abase = sbase + ((I % 3) * A_STG_W) * 4;
#pragma unroll
        for (int i = 0; i < 8; i++) {
            int idx = i * 256 + tid, row = idx >> 3, j = idx & 7;
            bool p = (trow + row) < M;
            uint32_t dw = row * 32 + ((4 * j) ^ swz(row));
            cp16(abase + dw * 4, &g_h16[(size_t)(trow + row) * 128 + c * 32 + 4 * j], p);
        }
    };

    issueA(0); CP_COMMIT();
    if (total_iters > 1) issueA(1);
    CP_COMMIT();

    float d[4][8][4];
#pragma unroll
    for (int mt = 0; mt < 4; mt++)
#pragma unroll
        for (int nt = 0; nt < 8; nt++)
#pragma unroll
            for (int q = 0; q < 4; q++) d[mt][nt][q] = 0.f;

    const int rb0 = warp_m * 64 + grp;
    const int nb0 = warp_n * 64 + grp;
    const __half2 zero2 = __floats2half2_rn(0.f, 0.f);

    for (int I = 0; I < total_iters; I++) {
        CP_WAIT1();
        __syncthreads();
        if (I + 2 < total_iters) issueA(I + 2);
        CP_COMMIT();
        const uint32_t* As = sm + (I % 3) * A_STG_W;
        const uint32_t* Bs = sm + B_OFF_W + (I & 3) * B_BC_W;
        const int c = I & 3;
#pragma unroll
        for (int cc = 0; cc < 2; cc++) {
#pragma unroll
            for (int s = 0; s < 2; s++) {
                const int lw0 = cc * 16 + s * 8 + tig, lw1 = lw0 + 4;
                const int kp0 = c * 32 + lw0, kp1 = c * 32 + lw1;
                const __half2 sc0 = scs2[kp0], sh0 = shs2[kp0];
                const __half2 sc1 = scs2[kp1], sh1 = shs2[kp1];
                uint32_t a[4][4], b[8][2];
#pragma unroll
                for (int mt = 0; mt < 4; mt++) {
                    int r = rb0 + mt * 16;
                    int z0 = swz(r), z1 = swz(r + 8);
                    __half2 h0 = *reinterpret_cast<const __half2*>(&As[r * 32 + (lw0 ^ z0)]);
                    __half2 h1 = *reinterpret_cast<const __half2*>(&As[(r + 8) * 32 + (lw0 ^ z1)]);
                    __half2 h2 = *reinterpret_cast<const __half2*>(&As[r * 32 + (lw1 ^ z0)]);
                    __half2 h3 = *reinterpret_cast<const __half2*>(&As[(r + 8) * 32 + (lw1 ^ z1)]);
                    h0 = __hmax2(__hfma2(h0, sc0, sh0), zero2);
                    h1 = __hmax2(__hfma2(h1, sc0, sh0), zero2);
                    h2 = __hmax2(__hfma2(h2, sc1, sh1), zero2);
                    h3 = __hmax2(__hfma2(h3, sc1, sh1), zero2);
                    a[mt][0] = *reinterpret_cast<uint32_t*>(&h0);
                    a[mt][1] = *reinterpret_cast<uint32_t*>(&h1);
                    a[mt][2] = *reinterpret_cast<uint32_t*>(&h2);
                    a[mt][3] = *reinterpret_cast<uint32_t*>(&h3);
                }
#pragma unroll
                for (int nt = 0; nt < 8; nt++) {
                    int nb = nb0 + nt * 8;
                    int zn = swz(nb);
                    b[nt][0] = Bs[nb * 32 + (lw0 ^ zn)];
                    b[nt][1] = Bs[nb * 32 + (lw1 ^ zn)];
                }
#pragma unroll
                for (int mt = 0; mt < 4; mt++)
#pragma unroll
                    for (int nt = 0; nt < 8; nt++) mma_f16(d[mt][nt], a[mt], b[nt]);
            }
        }

        if ((I & 3) == 3) {
            int trow = (by + (I >> 2) * bstride) * 256;
#pragma unroll
            for (int mt = 0; mt < 4; mt++) {
                int r0 = trow + warp_m * 64 + mt * 16 + grp;
#pragma unroll
                for (int nt = 0; nt < 8; nt++) {
                    int col = warp_n * 64 + nt * 8 + tig * 2;
                    float bx = b2[col], by2 = b2[col + 1];
                    if (r0 < M)
                        *reinterpret_cast<float2*>(&out[(size_t)r0 * N_D + col]) =
                            make_float2(d[mt][nt][0] + bx, d[mt][nt][1] + by2);
                    if (r0 + 8 < M)
                        *reinterpret_cast<float2*>(&out[(size_t)(r0 + 8) * N_D + col]) =
                            make_float2(d[mt][nt][2] + bx, d[mt][nt][3] + by2);
                    d[mt][nt][0] = 0.f; d[mt][nt][1] = 0.f;
                    d[mt][nt][2] = 0.f; d[mt][nt][3] = 0.f;
                }
            }
        }
    }
}

// ---------------------------------------------------------------------------
// Launch
// ---------------------------------------------------------------------------
extern "C" void kernel_launch(void* const* d_in, const int* in_sizes, int n_in,
                              void* d_out, int out_size) {
    const float* input  = (const float*)d_in[0];
    const int*   rows   = (const int*)  d_in[1];
    const int*   cols   = (const int*)  d_in[2];
    const float* vals   = (const float*)d_in[3];
    const float* gamma1 = (const float*)d_in[4];
    const float* beta1  = (const float*)d_in[5];
    const float* W1     = (const float*)d_in[6];
    const float* b1     = (const float*)d_in[7];
    const float* gamma2 = (const float*)d_in[8];
    const float* beta2  = (const float*)d_in[9];
    const float* W2     = (const float*)d_in[10];
    const float* b2     = (const float*)d_in[11];
    float* out = (float*)d_out;

    const int n = in_sizes[0] / N_D;
    const int E = in_sizes[1];
    const float n_inv = 1.0f / (float)n;

    cudaFuncSetAttribute(k_gemm1_mma, cudaFuncAttributeMaxDynamicSharedMemorySize, G1_SMEM);
    cudaFuncSetAttribute(k_gemm2_mma, cudaFuncAttributeMaxDynamicSharedMemorySize, G2_SMEM);

    // 0: zero agg/stats + input fp16 pack + weight staging
    {
        size_t n4 = (size_t)n * N_D / 4;
        size_t nw = (size_t)n * 64;
        k_zero_prep<<<(int)((n4 + 255) / 256), 256>>>(n4, nw, input, W1, W2);
    }
    // 1: SpMM (fp16 gathers)
    {
        int warps = (E + 7) / 8;
        k_spmm<<<(warps * 32 + 255) / 256, 256>>>(rows, cols, vals, E);
    }
    // 2: stats of x_cat + agg fp16 pack
    k_stats_cat<<<512, 128>>>(n);
    // 3: GEMM1 persistent fp16, BN1 fold in prologue  <- PROFILED
    {
        dim3 grid(2, 74);
        k_gemm1_mma<<<grid, 256, G1_SMEM>>>(gamma1, beta1, b1, n, n_inv);
    }
    // 4: GEMM2 persistent fp16
    {
        dim3 grid(1, 148);
        k_gemm2_mma<<<grid, 256, G2_SMEM>>>(gamma2, beta2, b2, out, n, n_inv);
    }
}

// round 15
// speedup vs baseline: 1.3099x; 1.0347x over previous
#include <cuda_runtime.h>
#include <cuda_fp16.h>
#include <cstdint>
#include <cstddef>

#define N_D   128
#define N_H   256
#define N_CAT 256
#define BN_EPS 1e-5f
#define MAXN  100000

// ---------------------------------------------------------------------------
// Scratch
// ---------------------------------------------------------------------------
__device__ __align__(1024) float    g_agg  [(size_t)MAXN * N_D];  // 51.2 MB f32
__device__ __align__(1024) uint32_t g_xin  [(size_t)MAXN * 64];   // 25.6 MB fp16 input
__device__ __align__(1024) uint32_t g_agg16[(size_t)MAXN * 64];   // 25.6 MB fp16 agg
__device__ __align__(1024) uint32_t g_h16  [(size_t)MAXN * 128];  // 51.2 MB fp16 h
__device__ float g_stats[4 * 256];
__device__ __align__(16) uint32_t g_W1t[N_H * N_CAT];   // raw W1^T (f32 bits)
__device__ __align__(16) uint32_t g_W2h[N_D * 128];     // W2^T fp16 pairs

// ---------------------------------------------------------------------------
// Helpers
// ---------------------------------------------------------------------------
__device__ __forceinline__ uint32_t smem_u32(const void* p) {
    uint32_t a;
    asm("{ .reg .u64 t; cvta.to.shared.u64 t, %1; cvt.u32.u64 %0, t; }" : "=r"(a) : "l"(p));
    return a;
}
__device__ __forceinline__ void cp16(uint32_t dst, const void* src, bool pred) {
    int sz = pred ? 16 : 0;
    asm volatile("cp.async.cg.shared.global [%0], [%1], 16, %2;"
                 :: "r"(dst), "l"(src), "r"(sz) : "memory");
}
#define CP_COMMIT() asm volatile("cp.async.commit_group;" ::: "memory")
#define CP_WAIT1()  asm volatile("cp.async.wait_group 1;" ::: "memory")
__device__ __forceinline__ uint32_t packh2(float x, float y) {
    __half2 h = __floats2half2_rn(x, y);
    return *reinterpret_cast<uint32_t*>(&h);
}
__device__ __forceinline__ void mma_f16(float d[4], const uint32_t a[4],
                                        const uint32_t b[2]) {
    asm volatile(
        "mma.sync.aligned.m16n8k16.row.col.f32.f16.f16.f32 "
        "{%0,%1,%2,%3}, {%4,%5,%6,%7}, {%8,%9}, {%0,%1,%2,%3};"
        : "+f"(d[0]), "+f"(d[1]), "+f"(d[2]), "+f"(d[3])
        : "r"(a[0]), "r"(a[1]), "r"(a[2]), "r"(a[3]), "r"(b[0]), "r"(b[1]));
}
__device__ __forceinline__ void ldsm_x4(uint32_t& r0, uint32_t& r1, uint32_t& r2,
                                        uint32_t& r3, uint32_t addr) {
    asm volatile("ldmatrix.sync.aligned.m8n8.x4.shared.b16 {%0,%1,%2,%3}, [%4];"
                 : "=r"(r0), "=r"(r1), "=r"(r2), "=r"(r3) : "r"(addr));
}
__device__ __forceinline__ int swz(int row) {
    return ((row & 6) << 1) ^ ((row & 1) << 4);
}

// ---------------------------------------------------------------------------
// Launch 0: zero agg+stats, pack input fp16, stage raw W1^T, pack W2^T fp16
// ---------------------------------------------------------------------------
__global__ void k_zero_prep(size_t n4, size_t nw, const float* __restrict__ input,
                            const float* __restrict__ W1, const float* __restrict__ W2) {
    size_t gid = (size_t)blockIdx.x * blockDim.x + threadIdx.x;
    size_t stride = (size_t)gridDim.x * blockDim.x;
    float4* p = reinterpret_cast<float4*>(g_agg);
    float4 z = make_float4(0.f, 0.f, 0.f, 0.f);
    for (size_t i = gid; i < n4; i += stride) p[i] = z;
    const float2* in2 = reinterpret_cast<const float2*>(input);
    for (size_t w = gid; w < nw; w += stride) {
        float2 v = in2[w];
        g_xin[w] = packh2(v.x, v.y);
    }
    int j = blockIdx.x, t = threadIdx.x;
    if (j == 0)
        for (int q = t; q < 4 * 256; q += blockDim.x) g_stats[q] = 0.f;
    if (j < 256) {
        g_W1t[(size_t)j * N_CAT + t] = __float_as_uint(W1[(size_t)t * N_H + j]);
    } else if (j < 384 && t < 128) {
        int n = j - 256;
        float w0 = W2[(size_t)(2 * t) * N_D + n];
        float w1 = W2[(size_t)(2 * t + 1) * N_D + n];
        g_W2h[(size_t)n * 128 + t] = packh2(w0, w1);
    }
}

// Launch 1: SpMM, 8 edges/warp, fp16 gathers, f32 reduction
__global__ void k_spmm(const int* __restrict__ rows, const int* __restrict__ cols,
                       const float* __restrict__ vals, int E) {
    int gw = (int)(((size_t)blockIdx.x * blockDim.x + threadIdx.x) >> 5);
    int lane = threadIdx.x & 31;
    int base = gw * 8;
    if (base >= E) return;

    int e = base + (lane & 7);
    bool ev = e < E;
    int c = ev ? cols[e] : 0;
    int r = ev ? rows[e] : 0;
    float v = ev ? vals[e] : 0.f;

    uint2 m[8];
    int ri[8];
    float vi[8];
#pragma unroll
    for (int i = 0; i < 8; i++) {
        int ci = __shfl_sync(0xffffffffu, c, i);
        ri[i]  = __shfl_sync(0xffffffffu, r, i);
        vi[i]  = __shfl_sync(0xffffffffu, v, i);
        m[i] = reinterpret_cast<const uint2*>(g_xin + (size_t)ci * 64)[lane];
    }
#pragma unroll
    for (int i = 0; i < 8; i++) {
        if (base + i < E) {
            float2 f0 = __half22float2(*reinterpret_cast<__half2*>(&m[i].x));
            float2 f1 = __half22float2(*reinterpret_cast<__half2*>(&m[i].y));
            float* dst = g_agg + (size_t)ri[i] * N_D + lane * 4;
            asm volatile("red.global.add.v4.f32 [%0], {%1,%2,%3,%4};"
                         :: "l"(dst), "f"(vi[i] * f0.x), "f"(vi[i] * f0.y),
                            "f"(vi[i] * f1.x), "f"(vi[i] * f1.y) : "memory");
        }
    }
}

// Launch 2: column stats of x_cat + pack agg half fp16
__global__ void k_stats_cat(int n) {
    int t = threadIdx.x;
    float s0 = 0.f, q0 = 0.f, s1 = 0.f, q1 = 0.f;
    if (t < 64) {
        for (int r = blockIdx.x; r < n; r += gridDim.x) {
            uint32_t w = g_xin[(size_t)r * 64 + t];
            float2 v = __half22float2(*reinterpret_cast<__half2*>(&w));
            s0 += v.x; q0 += v.x * v.x;
            s1 += v.y; q1 += v.y * v.y;
        }
    } else {
        int j = t - 64;
        for (int r = blockIdx.x; r < n; r += gridDim.x) {
            float2 v = *reinterpret_cast<const float2*>(g_agg + (size_t)r * N_D + 2 * j);
            s0 += v.x; q0 += v.x * v.x;
            s1 += v.y; q1 += v.y * v.y;
            g_agg16[(size_t)r * 64 + j] = packh2(v.x, v.y);
        }
    }
    atomicAdd(&g_stats[2 * t], s0);
    atomicAdd(&g_stats[2 * t + 1], s1);
    atomicAdd(&g_stats[256 + 2 * t], q0);
    atomicAdd(&g_stats[256 + 2 * t + 1], q1);
}

// ---------------------------------------------------------------------------
// Persistent fp16 GEMMs: K=64/iter, ldmatrix fragment loads, resident B.
// CTA 256 thr = 8 warps (4M x 2N), warp tile 64x64, M-tile 256, N-block 128.
// A: 3 stages x 256 rows x 32 words.  B: 4 K-panels x 128 rows x 32 words.
// Word swizzle: lw ^ ((row&6)<<1) ^ ((row&1)<<4)  (16B-granular).
// ---------------------------------------------------------------------------
#define A_STG_W   8192
#define B_OFF_W   24576
#define B_BC_W    4096
#define EXTRA_W   (B_OFF_W + 4 * B_BC_W)       // 40960
#define G1_SMEM   ((EXTRA_W + 512 + 128) * 4)
#define G2_SMEM   ((EXTRA_W + 256) * 4)

// Launch 3 (PROFILED): GEMM1 with in-kernel BN1 fold of the B panel.
__global__ __launch_bounds__(256, 1)
void k_gemm1_mma(const float* __restrict__ gamma1, const float* __restrict__ beta1,
                 const float* __restrict__ b1, int M, float n_inv) {
    extern __shared__ uint32_t sm[];
    const uint32_t sbase = smem_u32(sm);
    float* scs1 = reinterpret_cast<float*>(sm + EXTRA_W);
    float* shs1 = scs1 + 256;
    float* b1ps = shs1 + 256;
    const int tid = threadIdx.x, wid = tid >> 5, lane = tid & 31;
    const int warp_m = wid & 3, warp_n = wid >> 2;
    const int grp = lane >> 2, tig = lane & 3;
    const int block_col = blockIdx.x * 128;
    const int by = blockIdx.y, bstride = gridDim.y;
    const int ntiles = (M + 255) / 256;
    const int total_iters = ((ntiles - by + bstride - 1) / bstride) * 4;

    auto issueA = [&](int I) {
        int c = I & 3;
        int trow = (by + (I >> 2) * bstride) * 256;
        const uint32_t* asrc = (c < 2) ? g_xin : g_agg16;
        int kw = (c & 1) * 32;
        uint32_t abase = sbase + ((I % 3) * A_STG_W) * 4;
#pragma unroll
        for (int i = 0; i < 8; i++) {
            int idx = i * 256 + tid, row = idx >> 3, j = idx & 7;
            bool p = (trow + row) < M;
            uint32_t dw = row * 32 + ((4 * j) ^ swz(row));
            cp16(abase + dw * 4, asrc + (size_t)(trow + row) * 64 + kw + 4 * j, p);
        }
    };

    issueA(0); CP_COMMIT();
    if (total_iters > 1) issueA(1);
    CP_COMMIT();

    // BN1 params from stats
    {
        float mean = g_stats[tid] * n_inv;
        float var  = g_stats[256 + tid] * n_inv - mean * mean;
        float sc   = gamma1[tid] * rsqrtf(var + BN_EPS);
        scs1[tid] = sc;
        shs1[tid] = beta1[tid] - mean * sc;
    }
    __syncthreads();

    // Fold B panel into fp16 smem + b1p
    {
        int nrow = tid >> 1, half = tid & 1;
        int zn = swz(nrow);
        float bs = 0.f;
        const uint32_t* wrow = g_W1t + (size_t)(block_col + nrow) * N_CAT + half * 128;
#pragma unroll
        for (int i = 0; i < 32; i++) {
            int k = half * 128 + i * 4;
            float4 w4 = *reinterpret_cast<const float4*>(wrow + i * 4);
            uint32_t p0 = packh2(scs1[k] * w4.x, scs1[k + 1] * w4.y);
            uint32_t p1 = packh2(scs1[k + 2] * w4.z, scs1[k + 3] * w4.w);
            bs += shs1[k] * w4.x + shs1[k + 1] * w4.y
                + shs1[k + 2] * w4.z + shs1[k + 3] * w4.w;
            int bc = k >> 6, lw = (k & 63) >> 1;
            uint32_t base = B_OFF_W + bc * B_BC_W + nrow * 32 + (lw ^ zn);
            *reinterpret_cast<uint2*>(&sm[base]) = make_uint2(p0, p1);
        }
        bs += __shfl_xor_sync(0xffffffffu, bs, 1);
        if (half == 0) b1ps[nrow] = b1[block_col + nrow] + bs;
    }

    // ldmatrix per-lane row precompute
    uint32_t a_off[4], a_sw[4], b_off[4], b_sw[4];
    const int achunk = (lane >> 4) * 4;
    const int bchunk = ((lane >> 3) & 1) * 4;
#pragma unroll
    for (int mt = 0; mt < 4; mt++) {
        int r = warp_m * 64 + mt * 16 + (lane & 15);
        a_off[mt] = r * 32; a_sw[mt] = swz(r);
    }
#pragma unroll
    for (int p = 0; p < 4; p++) {
        int nb = warp_n * 64 + p * 16 + (lane & 7) + ((lane >> 4) << 3);
        b_off[p] = nb * 32; b_sw[p] = swz(nb);
    }

    float d[4][8][4];
#pragma unroll
    for (int mt = 0; mt < 4; mt++)
#pragma unroll
        for (int nt = 0; nt < 8; nt++)
#pragma unroll
            for (int q = 0; q < 4; q++) d[mt][nt][q] = 0.f;

    float cs[16], cq[16];
#pragma unroll
    for (int i = 0; i < 16; i++) { cs[i] = 0.f; cq[i] = 0.f; }

    __syncthreads();

    for (int I = 0; I < total_iters; I++) {
        CP_WAIT1();
        __syncthreads();
        if (I + 2 < total_iters) issueA(I + 2);
        CP_COMMIT();
        const uint32_t As_a = sbase + ((I % 3) * A_STG_W) * 4;
        const uint32_t Bs_a = sbase + (B_OFF_W + (I & 3) * B_BC_W) * 4;
#pragma unroll
        for (int sl = 0; sl < 4; sl++) {
            const int bw = sl * 8;
            uint32_t a[4][4], b[8][2];
#pragma unroll
            for (int mt = 0; mt < 4; mt++)
                ldsm_x4(a[mt][0], a[mt][1], a[mt][2], a[mt][3],
                        As_a + (a_off[mt] + ((bw + achunk) ^ a_sw[mt])) * 4);
#pragma unroll
            for (int p = 0; p < 4; p++)
                ldsm_x4(b[2 * p][0], b[2 * p][1], b[2 * p + 1][0], b[2 * p + 1][1],
                        Bs_a + (b_off[p] + ((bw + bchunk) ^ b_sw[p])) * 4);
#pragma unroll
            for (int mt = 0; mt < 4; mt++)
#pragma unroll
                for (int nt = 0; nt < 8; nt++) mma_f16(d[mt][nt], a[mt], b[nt]);
        }

        if ((I & 3) == 3) {
            int trow = (by + (I >> 2) * bstride) * 256;
#pragma unroll
            for (int mt = 0; mt < 4; mt++) {
                int r0 = trow + warp_m * 64 + mt * 16 + grp;
#pragma unroll
                for (int nt = 0; nt < 8; nt++) {
                    int lcol = warp_n * 64 + nt * 8 + tig * 2;
                    int col = block_col + lcol;
                    float bx = b1ps[lcol], by2 = b1ps[lcol + 1];
                    float vx = d[mt][nt][0] + bx, vy = d[mt][nt][1] + by2;
                    float vz = d[mt][nt][2] + bx, vw = d[mt][nt][3] + by2;
                    if (r0 < M) {
                        g_h16[(size_t)r0 * 128 + (col >> 1)] = packh2(vx, vy);
                        cs[nt * 2]     += vx;  cq[nt * 2]     += vx * vx;
                        cs[nt * 2 + 1] += vy;  cq[nt * 2 + 1] += vy * vy;
                    }
                    if (r0 + 8 < M) {
                        g_h16[(size_t)(r0 + 8) * 128 + (col >> 1)] = packh2(vz, vw);
                        cs[nt * 2]     += vz;  cq[nt * 2]     += vz * vz;
                        cs[nt * 2 + 1] += vw;  cq[nt * 2 + 1] += vw * vw;
                    }
                    d[mt][nt][0] = 0.f; d[mt][nt][1] = 0.f;
                    d[mt][nt][2] = 0.f; d[mt][nt][3] = 0.f;
                }
            }
        }
    }

#pragma unroll
    for (int i = 0; i < 16; i++) {
        float s = cs[i], q = cq[i];
        s += __shfl_xor_sync(0xffffffffu, s, 4);
        s += __shfl_xor_sync(0xffffffffu, s, 8);
        s += __shfl_xor_sync(0xffffffffu, s, 16);
        q += __shfl_xor_sync(0xffffffffu, q, 4);
        q += __shfl_xor_sync(0xffffffffu, q, 8);
        q += __shfl_xor_sync(0xffffffffu, q, 16);
        if (grp == 0) {
            int col = block_col + warp_n * 64 + (i >> 1) * 8 + tig * 2 + (i & 1);
            atomicAdd(&g_stats[512 + col], s);
            atomicAdd(&g_stats[768 + col], q);
        }
    }
}

// Launch 4: GEMM2: out = relu(h*sc2+sh2) @ W2h^T + b2 ; BN2 fp16 (HFMA2)
__global__ __launch_bounds__(256, 1)
void k_gemm2_mma(const float* __restrict__ gamma2, const float* __restrict__ beta2,
                 const float* __restrict__ b2, float* __restrict__ out,
                 int M, float n_inv) {
    extern __shared__ uint32_t sm[];
    const uint32_t sbase = smem_u32(sm);
    __half2* scs2 = reinterpret_cast<__half2*>(sm + EXTRA_W);
    __half2* shs2 = scs2 + 128;
    const int tid = threadIdx.x, wid = tid >> 5, lane = tid & 31;
    const int warp_m = wid & 3, warp_n = wid >> 2;
    const int grp = lane >> 2, tig = lane & 3;
    const int by = blockIdx.y, bstride = gridDim.y;
    const int ntiles = (M + 255) / 256;
    const int total_iters = ((ntiles - by + bstride - 1) / bstride) * 4;

    if (tid < 128) {
        int k0 = 2 * tid, k1 = k0 + 1;
        float m0 = g_stats[512 + k0] * n_inv;
        float v0 = g_stats[768 + k0] * n_inv - m0 * m0;
        float s0 = gamma2[k0] * rsqrtf(v0 + BN_EPS);
        float t0 = beta2[k0] - m0 * s0;
        float m1 = g_stats[512 + k1] * n_inv;
        float v1 = g_stats[768 + k1] * n_inv - m1 * m1;
        float s1 = gamma2[k1] * rsqrtf(v1 + BN_EPS);
        float t1 = beta2[k1] - m1 * s1;
        scs2[tid] = __floats2half2_rn(s0, s1);
        shs2[tid] = __floats2half2_rn(t0, t1);
    }

#pragma unroll
    for (int i = 0; i < 16; i++) {
        int idx = i * 256 + tid;
        int bc = idx >> 10, r2 = (idx >> 3) & 127, q = idx & 7;
        uint32_t dw = B_OFF_W + bc * B_BC_W + r2 * 32 + ((4 * q) ^ swz(r2));
        cp16(sbase + dw * 4, &g_W2h[(size_t)r2 * 128 + bc * 32 + 4 * q], true);
    }
    CP_COMMIT();

    auto issueA = [&](int I) {
        int c = I & 3;
        int trow = (by + (I >> 2) * bstride) * 256;
        uint32_t abase = sbase + ((I % 3) * A_STG_W) * 4;
#pragma unroll
        for (int i = 0; i < 8; i++) {
            int idx = i * 256 + tid, row = idx >> 3, j = idx & 7;
            bool p = (trow + row) < M;
            uint32_t dw = row * 32 + ((4 * j) ^ swz(row));
            cp16(abase + dw * 4, &g_h16[(size_t)(trow + row) * 128 + c * 32 + 4 * j], p);
        }
    };

    issueA(0); CP_COMMIT();
    if (total_iters > 1) issueA(1);
    CP_COMMIT();

    uint32_t a_off[4], a_sw[4], b_off[4], b_sw[4];
    const int achunk = (lane >> 4) * 4;
    const int bchunk = ((lane >> 3) & 1) * 4;
#pragma unroll
    for (int mt = 0; mt < 4; mt++) {
        int r = warp_m * 64 + mt * 16 + (lane & 15);
        a_off[mt] = r * 32; a_sw[mt] = swz(r);
    }
#pragma unroll
    for (int p = 0; p < 4; p++) {
        int nb = warp_n * 64 + p * 16 + (lane & 7) + ((lane >> 4) << 3);
        b_off[p] = nb * 32; b_sw[p] = swz(nb);
    }

    float d[4][8][4];
#pragma unroll
    for (int mt = 0; mt < 4; mt++)
#pragma unroll
        for (int nt = 0; nt < 8; nt++)
#pragma unroll
            for (int q = 0; q < 4; q++) d[mt][nt][q] = 0.f;

    const __half2 zero2 = __floats2half2_rn(0.f, 0.f);

    for (int I = 0; I < total_iters; I++) {
        CP_WAIT1();
        __syncthreads();
        if (I + 2 < total_iters) issueA(I + 2);
        CP_COMMIT();
        const uint32_t As_a = sbase + ((I % 3) * A_STG_W) * 4;
        const uint32_t Bs_a = sbase + (B_OFF_W + (I & 3) * B_BC_W) * 4;
        const int c = I & 3;
#pragma unroll
        for (int sl = 0; sl < 4; sl++) {
            const int bw = sl * 8;
            const int kp0 = c * 32 + bw + tig, kp1 = kp0 + 4;
            const __half2 sc0 = scs2[kp0], sh0 = shs2[kp0];
            const __half2 sc1 = scs2[kp1], sh1 = shs2[kp1];
            uint32_t a[4][4], b[8][2];
#pragma unroll
            for (int mt = 0; mt < 4; mt++) {
                ldsm_x4(a[mt][0], a[mt][1], a[mt][2], a[mt][3],
                        As_a + (a_off[mt] + ((bw + achunk) ^ a_sw[mt])) * 4);
                __half2 h0 = *reinterpret_cast<__half2*>(&a[mt][0]);
                __half2 h1 = *reinterpret_cast<__half2*>(&a[mt][1]);
                __half2 h2 = *reinterpret_cast<__half2*>(&a[mt][2]);
                __half2 h3 = *reinterpret_cast<__half2*>(&a[mt][3]);
                h0 = __hmax2(__hfma2(h0, sc0, sh0), zero2);
                h1 = __hmax2(__hfma2(h1, sc0, sh0), zero2);
                h2 = __hmax2(__hfma2(h2, sc1, sh1), zero2);
                h3 = __hmax2(__hfma2(h3, sc1, sh1), zero2);
                a[mt][0] = *reinterpret_cast<uint32_t*>(&h0);
                a[mt][1] = *reinterpret_cast<uint32_t*>(&h1);
                a[mt][2] = *reinterpret_cast<uint32_t*>(&h2);
                a[mt][3] = *reinterpret_cast<uint32_t*>(&h3);
            }
#pragma unroll
            for (int p = 0; p < 4; p++)
                ldsm_x4(b[2 * p][0], b[2 * p][1], b[2 * p + 1][0], b[2 * p + 1][1],
                        Bs_a + (b_off[p] + ((bw + bchunk) ^ b_sw[p])) * 4);
#pragma unroll
            for (int mt = 0; mt < 4; mt++)
#pragma unroll
                for (int nt = 0; nt < 8; nt++) mma_f16(d[mt][nt], a[mt], b[nt]);
        }

        if ((I & 3) == 3) {
            int trow = (by + (I >> 2) * bstride) * 256;
#pragma unroll
            for (int mt = 0; mt < 4; mt++) {
                int r0 = trow + warp_m * 64 + mt * 16 + grp;
#pragma unroll
                for (int nt = 0; nt < 8; nt++) {
                    int col = warp_n * 64 + nt * 8 + tig * 2;
                    float bx = b2[col], by2 = b2[col + 1];
                    if (r0 < M)
                        *reinterpret_cast<float2*>(&out[(size_t)r0 * N_D + col]) =
                            make_float2(d[mt][nt][0] + bx, d[mt][nt][1] + by2);
                    if (r0 + 8 < M)
                        *reinterpret_cast<float2*>(&out[(size_t)(r0 + 8) * N_D + col]) =
                            make_float2(d[mt][nt][2] + bx, d[mt][nt][3] + by2);
                    d[mt][nt][0] = 0.f; d[mt][nt][1] = 0.f;
                    d[mt][nt][2] = 0.f; d[mt][nt][3] = 0.f;
                }
            }
        }
    }
}

// ---------------------------------------------------------------------------
// Launch
// ---------------------------------------------------------------------------
extern "C" void kernel_launch(void* const* d_in, const int* in_sizes, int n_in,
                              void* d_out, int out_size) {
    const float* input  = (const float*)d_in[0];
    const int*   rows   = (const int*)  d_in[1];
    const int*   cols   = (const int*)  d_in[2];
    const float* vals   = (const float*)d_in[3];
    const float* gamma1 = (const float*)d_in[4];
    const float* beta1  = (const float*)d_in[5];
    const float* W1     = (const float*)d_in[6];
    const float* b1     = (const float*)d_in[7];
    const float* gamma2 = (const float*)d_in[8];
    const float* beta2  = (const float*)d_in[9];
    const float* W2     = (const float*)d_in[10];
    const float* b2     = (const float*)d_in[11];
    float* out = (float*)d_out;

    const int n = in_sizes[0] / N_D;
    const int E = in_sizes[1];
    const float n_inv = 1.0f / (float)n;

    cudaFuncSetAttribute(k_gemm1_mma, cudaFuncAttributeMaxDynamicSharedMemorySize, G1_SMEM);
    cudaFuncSetAttribute(k_gemm2_mma, cudaFuncAttributeMaxDynamicSharedMemorySize, G2_SMEM);

    // 0: zero agg/stats + input fp16 pack + weight staging
    {
        size_t n4 = (size_t)n * N_D / 4;
        size_t nw = (size_t)n * 64;
        k_zero_prep<<<(int)((n4 + 255) / 256), 256>>>(n4, nw, input, W1, W2);
    }
    // 1: SpMM (fp16 gathers)
    {
        int warps = (E + 7) / 8;
        k_spmm<<<(warps * 32 + 255) / 256, 256>>>(rows, cols, vals, E);
    }
    // 2: stats of x_cat + agg fp16 pack
    k_stats_cat<<<512, 128>>>(n);
    // 3: GEMM1 persistent fp16 + ldmatrix, BN1 fold in prologue  <- PROFILED
    {
        dim3 grid(2, 74);
        k_gemm1_mma<<<grid, 256, G1_SMEM>>>(gamma1, beta1, b1, n, n_inv);
    }
    // 4: GEMM2 persistent fp16 + ldmatrix
    {
        dim3 grid(1, 148);
        k_gemm2_mma<<<grid, 256, G2_SMEM>>>(gamma2, beta2, b2, out, n, n_inv);
    }
}